// round 4
// baseline (speedup 1.0000x reference)
#include <cuda_runtime.h>
#include <cuda_bf16.h>
#include <stdint.h>

// Problem constants
#define B_   2
#define N_   2048
#define E_   1024
#define H_   16
#define HD_  64
#define M_TOT  (B_ * N_)     // 4096
#define QKV_N  (3 * E_)      // 3072
#define BH_    (B_ * H_)     // 32

// ---------------------------------------------------------------------------
// Device scratch (allocation-free rule)
// ---------------------------------------------------------------------------
__device__ int8_t g_a1[(size_t)M_TOT * E_];
__device__ int8_t g_a0[(size_t)M_TOT * E_];
__device__ int8_t g_wq1[(size_t)QKV_N * E_];
__device__ int8_t g_wq0[(size_t)QKV_N * E_];
__device__ int8_t g_wo1[(size_t)E_ * E_];
__device__ int8_t g_wo0[(size_t)E_ * E_];
__device__ int8_t g_o1[(size_t)M_TOT * E_];
__device__ int8_t g_o0[(size_t)M_TOT * E_];
__device__ float g_sa[M_TOT];
__device__ float g_swq[QKV_N];
__device__ float g_swo[E_];
__device__ float g_so[M_TOT];
__device__ float g_tmpT[(size_t)QKV_N * E_];   // transposed-weight staging
__device__ float g_qkv[(size_t)M_TOT * QKV_N];
__device__ float g_att[(size_t)M_TOT * E_];
__device__ __nv_bfloat16 g_qh[(size_t)BH_ * N_ * HD_];
__device__ __nv_bfloat16 g_ql[(size_t)BH_ * N_ * HD_];
__device__ __nv_bfloat16 g_kh[(size_t)BH_ * N_ * HD_];
__device__ __nv_bfloat16 g_kl[(size_t)BH_ * N_ * HD_];
__device__ __nv_bfloat16 g_vth[(size_t)BH_ * HD_ * N_];
__device__ __nv_bfloat16 g_vtl[(size_t)BH_ * HD_ * N_];

// ---------------------------------------------------------------------------
// Helpers
// ---------------------------------------------------------------------------
__device__ __forceinline__ uint32_t smem_u32(const void* p) {
    uint32_t a;
    asm("{ .reg .u64 t; cvta.to.shared.u64 t, %1; cvt.u32.u64 %0, t; }"
        : "=r"(a) : "l"(p));
    return a;
}

__device__ __forceinline__ void mma16816(float c[4], const uint32_t a[4],
                                         const uint32_t b[2]) {
    asm volatile(
        "mma.sync.aligned.m16n8k16.row.col.f32.bf16.bf16.f32 "
        "{%0,%1,%2,%3},{%4,%5,%6,%7},{%8,%9},{%0,%1,%2,%3};"
        : "+f"(c[0]), "+f"(c[1]), "+f"(c[2]), "+f"(c[3])
        : "r"(a[0]), "r"(a[1]), "r"(a[2]), "r"(a[3]), "r"(b[0]), "r"(b[1]));
}

__device__ __forceinline__ void imma16832(int c[4], const uint32_t a[4],
                                          const uint32_t b[2]) {
    asm volatile(
        "mma.sync.aligned.m16n8k32.row.col.s32.s8.s8.s32 "
        "{%0,%1,%2,%3},{%4,%5,%6,%7},{%8,%9},{%0,%1,%2,%3};"
        : "+r"(c[0]), "+r"(c[1]), "+r"(c[2]), "+r"(c[3])
        : "r"(a[0]), "r"(a[1]), "r"(a[2]), "r"(a[3]), "r"(b[0]), "r"(b[1]));
}

__device__ __forceinline__ void ldsm4(uint32_t r[4], const void* p) {
    uint32_t a = smem_u32(p);
    asm volatile("ldmatrix.sync.aligned.m8n8.x4.shared.b16 {%0,%1,%2,%3},[%4];"
                 : "=r"(r[0]), "=r"(r[1]), "=r"(r[2]), "=r"(r[3])
                 : "r"(a));
}

__device__ __forceinline__ void cpa16(uint32_t s, const void* g) {
    asm volatile("cp.async.cg.shared.global [%0],[%1],16;" ::"r"(s), "l"(g));
}

__device__ __forceinline__ float ex2f(float x) {
    float r;
    asm("ex2.approx.ftz.f32 %0,%1;" : "=f"(r) : "f"(x));
    return r;
}

__device__ __forceinline__ void split2(float x, float y, uint32_t& hi, uint32_t& lo) {
    __nv_bfloat16 xh = __float2bfloat16(x);
    __nv_bfloat16 yh = __float2bfloat16(y);
    float xr = x - __bfloat162float(xh);
    float yr = y - __bfloat162float(yh);
    __nv_bfloat162 h2, l2;
    h2.x = xh; h2.y = yh;
    l2.x = __float2bfloat16(xr); l2.y = __float2bfloat16(yr);
    hi = *reinterpret_cast<uint32_t*>(&h2);
    lo = *reinterpret_cast<uint32_t*>(&l2);
}

// ---------------------------------------------------------------------------
// 1) Per-row 2-level int8 quantization. K must be 1024; 256 threads/row.
//    A[row] ~= S[row] * (128*Q1 + Q0)
// ---------------------------------------------------------------------------
__global__ __launch_bounds__(256)
void quant_rows_kernel(const float* __restrict__ A, int8_t* __restrict__ Q1,
                       int8_t* __restrict__ Q0, float* __restrict__ S, int K) {
    __shared__ float wm[8];
    const int row = blockIdx.x, t = threadIdx.x;
    const int lane = t & 31, w = t >> 5;
    const float4 v = ((const float4*)(A + (size_t)row * K))[t];

    float m = fmaxf(fmaxf(fabsf(v.x), fabsf(v.y)), fmaxf(fabsf(v.z), fabsf(v.w)));
#pragma unroll
    for (int o = 16; o > 0; o >>= 1) m = fmaxf(m, __shfl_xor_sync(~0u, m, o));
    if (lane == 0) wm[w] = m;
    __syncthreads();
    float mall = wm[0];
#pragma unroll
    for (int i = 1; i < 8; i++) mall = fmaxf(mall, wm[i]);

    const float inv = (mall > 0.f) ? 16256.f / mall : 0.f;
    if (t == 0) S[row] = (mall > 0.f) ? mall / 16256.f : 0.f;

    char4 c1, c0;
    float q, h;
    q = rintf(v.x * inv); h = rintf(q * 0.0078125f);
    c1.x = (int8_t)(int)h; c0.x = (int8_t)(int)(q - 128.f * h);
    q = rintf(v.y * inv); h = rintf(q * 0.0078125f);
    c1.y = (int8_t)(int)h; c0.y = (int8_t)(int)(q - 128.f * h);
    q = rintf(v.z * inv); h = rintf(q * 0.0078125f);
    c1.z = (int8_t)(int)h; c0.z = (int8_t)(int)(q - 128.f * h);
    q = rintf(v.w * inv); h = rintf(q * 0.0078125f);
    c1.w = (int8_t)(int)h; c0.w = (int8_t)(int)(q - 128.f * h);
    ((char4*)(Q1 + (size_t)row * K))[t] = c1;
    ((char4*)(Q0 + (size_t)row * K))[t] = c0;
}

// ---------------------------------------------------------------------------
// 2) Transpose W[K,N] -> T[N,K] (f32)
// ---------------------------------------------------------------------------
__global__ __launch_bounds__(256)
void transpose_kernel(const float* __restrict__ W, float* __restrict__ T,
                      int K, int N) {
    __shared__ float t[32][33];
    int k0 = blockIdx.y * 32, n0 = blockIdx.x * 32;
    int tx = threadIdx.x & 31, ty = threadIdx.x >> 5;
#pragma unroll
    for (int i = 0; i < 4; i++)
        t[ty + 8 * i][tx] = W[(size_t)(k0 + ty + 8 * i) * N + n0 + tx];
    __syncthreads();
#pragma unroll
    for (int i = 0; i < 4; i++)
        T[(size_t)(n0 + ty + 8 * i) * K + k0 + tx] = t[tx][ty + 8 * i];
}

// ---------------------------------------------------------------------------
// 3) Int8 2-level IMMA GEMM: C = sA.sB.(16384*A1B1 + 128*(A1B0+A0B1)) + bias
//    BM=BN=128, BK=32, 256 thr, 2-stage cp.async double buffer.
// ---------------------------------------------------------------------------
__global__ __launch_bounds__(256)
void gemm_i8_kernel(const int8_t* __restrict__ A1, const int8_t* __restrict__ A0,
                    const int8_t* __restrict__ B1, const int8_t* __restrict__ B0,
                    const float* __restrict__ sA, const float* __restrict__ sB,
                    const float* __restrict__ bias, float* __restrict__ C,
                    int M, int N, int K) {
    __shared__ int8_t sm[2][4][128][48];   // 48KB; arrays A1,A0,B1,B0 (32B + pad)
    const int tid = threadIdx.x, lane = tid & 31, w = tid >> 5;
    const int wm = w >> 2, wn = w & 3;     // 2 x 4 warp grid
    const int brow = blockIdx.y * 128, bcol = blockIdx.x * 128;

    int ch[4][4][4] = {};
    int cm[4][4][4] = {};

    auto load_stage = [&](int s, int k0) {
        const int8_t* ptrs[4] = {
            A1 + (size_t)brow * K, A0 + (size_t)brow * K,
            B1 + (size_t)bcol * K, B0 + (size_t)bcol * K};
        int row = tid >> 1, c16 = (tid & 1) * 16;
#pragma unroll
        for (int arr = 0; arr < 4; arr++)
            cpa16(smem_u32(&sm[s][arr][row][c16]),
                  ptrs[arr] + (size_t)row * K + k0 + c16);
        asm volatile("cp.async.commit_group;");
    };

    const int NIT = K >> 5;
    load_stage(0, 0);
    for (int it = 0; it < NIT; ++it) {
        if (it + 1 < NIT) {
            load_stage((it + 1) & 1, (it + 1) * 32);
            asm volatile("cp.async.wait_group 1;");
        } else {
            asm volatile("cp.async.wait_group 0;");
        }
        __syncthreads();
        int s = it & 1;

        uint32_t a1f[4][4], a0f[4][4];
#pragma unroll
        for (int mt = 0; mt < 4; mt++) {
            int row = wm * 64 + mt * 16 + (lane & 15);
            int col = (lane >> 4) * 16;
            ldsm4(a1f[mt], &sm[s][0][row][col]);
            ldsm4(a0f[mt], &sm[s][1][row][col]);
        }
        uint32_t b1f[4][2], b0f[4][2];
#pragma unroll
        for (int p = 0; p < 2; p++) {
            int row = wn * 32 + p * 16 + (lane & 15);
            int col = (lane >> 4) * 16;
            uint32_t t[4];
            ldsm4(t, &sm[s][2][row][col]);
            b1f[2 * p][0] = t[0]; b1f[2 * p][1] = t[2];
            b1f[2 * p + 1][0] = t[1]; b1f[2 * p + 1][1] = t[3];
            ldsm4(t, &sm[s][3][row][col]);
            b0f[2 * p][0] = t[0]; b0f[2 * p][1] = t[2];
            b0f[2 * p + 1][0] = t[1]; b0f[2 * p + 1][1] = t[3];
        }
#pragma unroll
        for (int mt = 0; mt < 4; mt++)
#pragma unroll
            for (int nt = 0; nt < 4; nt++) {
                imma16832(ch[mt][nt], a1f[mt], b1f[nt]);
                imma16832(cm[mt][nt], a1f[mt], b0f[nt]);
                imma16832(cm[mt][nt], a0f[mt], b1f[nt]);
            }
        __syncthreads();
    }

    // Epilogue: scale + bias
#pragma unroll
    for (int mt = 0; mt < 4; mt++) {
        int r0 = brow + wm * 64 + mt * 16 + (lane >> 2);
        float sa0 = sA[r0], sa1 = sA[r0 + 8];
#pragma unroll
        for (int nt = 0; nt < 4; nt++) {
            int col = bcol + wn * 32 + nt * 8 + 2 * (lane & 3);
            float sb0 = sB[col], sb1 = sB[col + 1];
            float bi0 = bias[col], bi1 = bias[col + 1];
            float2 v0, v1;
            v0.x = sa0 * sb0 * (16384.f * (float)ch[mt][nt][0] + 128.f * (float)cm[mt][nt][0]) + bi0;
            v0.y = sa0 * sb1 * (16384.f * (float)ch[mt][nt][1] + 128.f * (float)cm[mt][nt][1]) + bi1;
            v1.x = sa1 * sb0 * (16384.f * (float)ch[mt][nt][2] + 128.f * (float)cm[mt][nt][2]) + bi0;
            v1.y = sa1 * sb1 * (16384.f * (float)ch[mt][nt][3] + 128.f * (float)cm[mt][nt][3]) + bi1;
            *(float2*)(C + (size_t)r0 * N + col) = v0;
            *(float2*)(C + (size_t)(r0 + 8) * N + col) = v1;
        }
    }
}

// ---------------------------------------------------------------------------
// 4) Repack qkv fp32 -> per-head Q(scaled)/K bf16 hi/lo, V^T hi/lo
// ---------------------------------------------------------------------------
__global__ __launch_bounds__(256)
void repack_kernel(const float* __restrict__ qkv,
                   __nv_bfloat16* __restrict__ Qh, __nv_bfloat16* __restrict__ Ql,
                   __nv_bfloat16* __restrict__ Kh, __nv_bfloat16* __restrict__ Kl,
                   __nv_bfloat16* __restrict__ Vth, __nv_bfloat16* __restrict__ Vtl) {
    __shared__ float vt[64][65];
    const int bh = blockIdx.y;
    const int b = bh >> 4, h = bh & 15;
    const int nb = blockIdx.x * 64;
    const float qscale = 0.125f * 1.4426950408889634f;

    for (int idx = threadIdx.x; idx < 64 * 192; idx += 256) {
        int r = idx / 192, cc = idx % 192;
        float v = qkv[(size_t)(b * N_ + nb + r) * QKV_N + h * 192 + cc];
        if (cc < 64) {
            float vq = v * qscale;
            __nv_bfloat16 hi = __float2bfloat16(vq);
            size_t o = ((size_t)bh * N_ + nb + r) * 64 + cc;
            Qh[o] = hi;
            Ql[o] = __float2bfloat16(vq - __bfloat162float(hi));
        } else if (cc < 128) {
            __nv_bfloat16 hi = __float2bfloat16(v);
            size_t o = ((size_t)bh * N_ + nb + r) * 64 + (cc - 64);
            Kh[o] = hi;
            Kl[o] = __float2bfloat16(v - __bfloat162float(hi));
        } else {
            vt[cc - 128][r] = v;
        }
    }
    __syncthreads();
    for (int idx = threadIdx.x; idx < 64 * 64; idx += 256) {
        int d = idx >> 6, nl = idx & 63;
        float v = vt[d][nl];
        __nv_bfloat16 hi = __float2bfloat16(v);
        size_t o = ((size_t)bh * 64 + d) * N_ + nb + nl;
        Vth[o] = hi;
        Vtl[o] = __float2bfloat16(v - __bfloat162float(hi));
    }
}

// ---------------------------------------------------------------------------
// 5) FA2-style attention with split-bf16 mma.sync; f32 output [M_TOT, E].
// ---------------------------------------------------------------------------
__global__ __launch_bounds__(256)
void attn_kernel(const __nv_bfloat16* __restrict__ Qh, const __nv_bfloat16* __restrict__ Ql,
                 const __nv_bfloat16* __restrict__ Kh, const __nv_bfloat16* __restrict__ Kl,
                 const __nv_bfloat16* __restrict__ Vth, const __nv_bfloat16* __restrict__ Vtl,
                 float* __restrict__ O) {
    __shared__ __nv_bfloat16 ks[2][64][72];
    __shared__ __nv_bfloat16 vs[2][64][72];
    const int tid = threadIdx.x, lane = tid & 31, w = tid >> 5;
    const int bh = blockIdx.y, qb = blockIdx.x;
    const size_t qkbase = (size_t)bh * N_ * 64;
    const size_t vbase = (size_t)bh * 64 * N_;

    uint32_t qh[4][4], ql[4][4];
    {
        int r0 = qb * 128 + w * 16 + (lane >> 2);
        int c0 = 2 * (lane & 3);
#pragma unroll
        for (int kd = 0; kd < 4; kd++) {
            const __nv_bfloat16* ph = Qh + qkbase + (size_t)r0 * 64 + kd * 16 + c0;
            const __nv_bfloat16* pl = Ql + qkbase + (size_t)r0 * 64 + kd * 16 + c0;
            qh[kd][0] = *(const uint32_t*)(ph);
            qh[kd][1] = *(const uint32_t*)(ph + 8 * 64);
            qh[kd][2] = *(const uint32_t*)(ph + 8);
            qh[kd][3] = *(const uint32_t*)(ph + 8 * 64 + 8);
            ql[kd][0] = *(const uint32_t*)(pl);
            ql[kd][1] = *(const uint32_t*)(pl + 8 * 64);
            ql[kd][2] = *(const uint32_t*)(pl + 8);
            ql[kd][3] = *(const uint32_t*)(pl + 8 * 64 + 8);
        }
    }

    float m0 = -1e30f, m1 = -1e30f, l0 = 0.f, l1 = 0.f;
    float o[8][4] = {};

    for (int kt0 = 0; kt0 < N_; kt0 += 64) {
        __syncthreads();
#pragma unroll
        for (int i = 0; i < 8; i++) {
            int ch = tid + i * 256;
            int arr = ch >> 9;
            int r = (ch & 511) >> 3;
            int h8 = (ch & 7) * 8;
            if (arr == 0)
                *(float4*)&ks[0][r][h8] = *(const float4*)(Kh + qkbase + (size_t)(kt0 + r) * 64 + h8);
            else if (arr == 1)
                *(float4*)&ks[1][r][h8] = *(const float4*)(Kl + qkbase + (size_t)(kt0 + r) * 64 + h8);
            else if (arr == 2)
                *(float4*)&vs[0][r][h8] = *(const float4*)(Vth + vbase + (size_t)r * N_ + kt0 + h8);
            else
                *(float4*)&vs[1][r][h8] = *(const float4*)(Vtl + vbase + (size_t)r * N_ + kt0 + h8);
        }
        __syncthreads();

        float s[8][4] = {};
#pragma unroll
        for (int kd = 0; kd < 4; kd++) {
            uint32_t kbh[8][2], kbl[8][2];
#pragma unroll
            for (int p = 0; p < 4; p++) {
                int row = p * 16 + (lane & 15);
                int col = kd * 16 + (lane >> 4) * 8;
                uint32_t t[4];
                ldsm4(t, &ks[0][row][col]);
                kbh[2 * p][0] = t[0]; kbh[2 * p][1] = t[2];
                kbh[2 * p + 1][0] = t[1]; kbh[2 * p + 1][1] = t[3];
                ldsm4(t, &ks[1][row][col]);
                kbl[2 * p][0] = t[0]; kbl[2 * p][1] = t[2];
                kbl[2 * p + 1][0] = t[1]; kbl[2 * p + 1][1] = t[3];
            }
#pragma unroll
            for (int nt = 0; nt < 8; nt++) {
                mma16816(s[nt], qh[kd], kbh[nt]);
                mma16816(s[nt], qh[kd], kbl[nt]);
                mma16816(s[nt], ql[kd], kbh[nt]);
            }
        }

        float mx0 = -1e30f, mx1 = -1e30f;
#pragma unroll
        for (int nt = 0; nt < 8; nt++) {
            mx0 = fmaxf(mx0, fmaxf(s[nt][0], s[nt][1]));
            mx1 = fmaxf(mx1, fmaxf(s[nt][2], s[nt][3]));
        }
        mx0 = fmaxf(mx0, __shfl_xor_sync(0xffffffffu, mx0, 1));
        mx0 = fmaxf(mx0, __shfl_xor_sync(0xffffffffu, mx0, 2));
        mx1 = fmaxf(mx1, __shfl_xor_sync(0xffffffffu, mx1, 1));
        mx1 = fmaxf(mx1, __shfl_xor_sync(0xffffffffu, mx1, 2));
        float mn0 = fmaxf(m0, mx0), mn1 = fmaxf(m1, mx1);
        float a0 = ex2f(m0 - mn0), a1 = ex2f(m1 - mn1);
        m0 = mn0; m1 = mn1;

        float sum0 = 0.f, sum1 = 0.f;
#pragma unroll
        for (int nt = 0; nt < 8; nt++) {
            s[nt][0] = ex2f(s[nt][0] - mn0);
            s[nt][1] = ex2f(s[nt][1] - mn0);
            s[nt][2] = ex2f(s[nt][2] - mn1);
            s[nt][3] = ex2f(s[nt][3] - mn1);
            sum0 += s[nt][0] + s[nt][1];
            sum1 += s[nt][2] + s[nt][3];
        }
        sum0 += __shfl_xor_sync(0xffffffffu, sum0, 1);
        sum0 += __shfl_xor_sync(0xffffffffu, sum0, 2);
        sum1 += __shfl_xor_sync(0xffffffffu, sum1, 1);
        sum1 += __shfl_xor_sync(0xffffffffu, sum1, 2);
        l0 = l0 * a0 + sum0;
        l1 = l1 * a1 + sum1;
#pragma unroll
        for (int nd = 0; nd < 8; nd++) {
            o[nd][0] *= a0; o[nd][1] *= a0;
            o[nd][2] *= a1; o[nd][3] *= a1;
        }

        uint32_t pah[4][4], pal[4][4];
#pragma unroll
        for (int kt = 0; kt < 4; kt++) {
            split2(s[2 * kt][0], s[2 * kt][1], pah[kt][0], pal[kt][0]);
            split2(s[2 * kt][2], s[2 * kt][3], pah[kt][1], pal[kt][1]);
            split2(s[2 * kt + 1][0], s[2 * kt + 1][1], pah[kt][2], pal[kt][2]);
            split2(s[2 * kt + 1][2], s[2 * kt + 1][3], pah[kt][3], pal[kt][3]);
        }

#pragma unroll
        for (int kt = 0; kt < 4; kt++) {
            uint32_t vbh[8][2], vbl[8][2];
#pragma unroll
            for (int p = 0; p < 4; p++) {
                int row = p * 16 + (lane & 15);
                int col = kt * 16 + (lane >> 4) * 8;
                uint32_t t[4];
                ldsm4(t, &vs[0][row][col]);
                vbh[2 * p][0] = t[0]; vbh[2 * p][1] = t[2];
                vbh[2 * p + 1][0] = t[1]; vbh[2 * p + 1][1] = t[3];
                ldsm4(t, &vs[1][row][col]);
                vbl[2 * p][0] = t[0]; vbl[2 * p][1] = t[2];
                vbl[2 * p + 1][0] = t[1]; vbl[2 * p + 1][1] = t[3];
            }
#pragma unroll
            for (int nd = 0; nd < 8; nd++) {
                mma16816(o[nd], pah[kt], vbh[nd]);
                mma16816(o[nd], pah[kt], vbl[nd]);
                mma16816(o[nd], pal[kt], vbh[nd]);
            }
        }
    }

    float i0 = 1.f / l0, i1 = 1.f / l1;
    int b = bh >> 4, h = bh & 15;
    int r0 = b * N_ + qb * 128 + w * 16 + (lane >> 2);
#pragma unroll
    for (int nd = 0; nd < 8; nd++) {
        int col = h * 64 + nd * 8 + 2 * (lane & 3);
        *(float2*)(O + (size_t)r0 * E_ + col) = make_float2(o[nd][0] * i0, o[nd][1] * i0);
        *(float2*)(O + (size_t)(r0 + 8) * E_ + col) = make_float2(o[nd][2] * i1, o[nd][3] * i1);
    }
}

// ---------------------------------------------------------------------------
extern "C" void kernel_launch(void* const* d_in, const int* in_sizes, int n_in,
                              void* d_out, int out_size) {
    (void)in_sizes; (void)n_in; (void)out_size;
    const float* x     = (const float*)d_in[0];
    const float* W_qkv = (const float*)d_in[1];
    const float* b_qkv = (const float*)d_in[2];
    const float* W_out = (const float*)d_in[3];
    const float* b_out = (const float*)d_in[4];
    float* out = (float*)d_out;

    int8_t *a1, *a0, *wq1, *wq0, *wo1, *wo0, *o1, *o0;
    float *sa, *swq, *swo, *so, *tmpT, *qkv, *att;
    __nv_bfloat16 *q_h, *q_l, *k_h, *k_l, *vt_h, *vt_l;
    cudaGetSymbolAddress((void**)&a1, g_a1);
    cudaGetSymbolAddress((void**)&a0, g_a0);
    cudaGetSymbolAddress((void**)&wq1, g_wq1);
    cudaGetSymbolAddress((void**)&wq0, g_wq0);
    cudaGetSymbolAddress((void**)&wo1, g_wo1);
    cudaGetSymbolAddress((void**)&wo0, g_wo0);
    cudaGetSymbolAddress((void**)&o1, g_o1);
    cudaGetSymbolAddress((void**)&o0, g_o0);
    cudaGetSymbolAddress((void**)&sa, g_sa);
    cudaGetSymbolAddress((void**)&swq, g_swq);
    cudaGetSymbolAddress((void**)&swo, g_swo);
    cudaGetSymbolAddress((void**)&so, g_so);
    cudaGetSymbolAddress((void**)&tmpT, g_tmpT);
    cudaGetSymbolAddress((void**)&qkv, g_qkv);
    cudaGetSymbolAddress((void**)&att, g_att);
    cudaGetSymbolAddress((void**)&q_h, g_qh);
    cudaGetSymbolAddress((void**)&q_l, g_ql);
    cudaGetSymbolAddress((void**)&k_h, g_kh);
    cudaGetSymbolAddress((void**)&k_l, g_kl);
    cudaGetSymbolAddress((void**)&vt_h, g_vth);
    cudaGetSymbolAddress((void**)&vt_l, g_vtl);

    // Quantize x; transpose + quantize weights
    quant_rows_kernel<<<M_TOT, 256>>>(x, a1, a0, sa, E_);
    transpose_kernel<<<dim3(QKV_N / 32, E_ / 32), 256>>>(W_qkv, tmpT, E_, QKV_N);
    quant_rows_kernel<<<QKV_N, 256>>>(tmpT, wq1, wq0, swq, E_);
    transpose_kernel<<<dim3(E_ / 32, E_ / 32), 256>>>(W_out, tmpT, E_, E_);
    quant_rows_kernel<<<E_, 256>>>(tmpT, wo1, wo0, swo, E_);

    // QKV projection (int8 IMMA)
    gemm_i8_kernel<<<dim3(QKV_N / 128, M_TOT / 128), 256>>>(
        a1, a0, wq1, wq0, sa, swq, b_qkv, qkv, M_TOT, QKV_N, E_);

    // Repack into per-head layouts
    repack_kernel<<<dim3(N_ / 64, BH_), 256>>>(qkv, q_h, q_l, k_h, k_l, vt_h, vt_l);

    // Attention (split-bf16 mma.sync) -> f32 g_att
    attn_kernel<<<dim3(N_ / 128, BH_), 256>>>(q_h, q_l, k_h, k_l, vt_h, vt_l, att);

    // Quantize attention output, output projection (int8 IMMA)
    quant_rows_kernel<<<M_TOT, 256>>>(att, o1, o0, so, E_);
    gemm_i8_kernel<<<dim3(E_ / 128, M_TOT / 128), 256>>>(
        o1, o0, wo1, wo0, so, swo, b_out, out, M_TOT, E_, E_);
}

// round 5
// speedup vs baseline: 1.2398x; 1.2398x over previous
#include <cuda_runtime.h>
#include <cuda_bf16.h>
#include <cuda_fp16.h>
#include <stdint.h>

// Problem constants
#define B_   2
#define N_   2048
#define E_   1024
#define H_   16
#define HD_  64
#define M_TOT  (B_ * N_)     // 4096
#define QKV_N  (3 * E_)      // 3072
#define BH_    (B_ * H_)     // 32

// ---------------------------------------------------------------------------
// Device scratch (allocation-free rule)
// ---------------------------------------------------------------------------
__device__ __nv_bfloat16 g_wqkv_h[(size_t)QKV_N * E_];
__device__ __nv_bfloat16 g_wqkv_l[(size_t)QKV_N * E_];
__device__ __nv_bfloat16 g_wout_h[(size_t)E_ * E_];
__device__ __nv_bfloat16 g_wout_l[(size_t)E_ * E_];
__device__ __nv_bfloat16 g_xh[(size_t)M_TOT * E_];
__device__ __nv_bfloat16 g_xl[(size_t)M_TOT * E_];
__device__ float g_qkv[(size_t)M_TOT * QKV_N];
__device__ __half g_qf[(size_t)BH_ * N_ * HD_];
__device__ __half g_kf[(size_t)BH_ * N_ * HD_];
__device__ __half g_vth[(size_t)BH_ * HD_ * N_];
__device__ __half g_vtl[(size_t)BH_ * HD_ * N_];
__device__ __nv_bfloat16 g_oh[(size_t)M_TOT * E_];
__device__ __nv_bfloat16 g_ol[(size_t)M_TOT * E_];

// ---------------------------------------------------------------------------
// Helpers
// ---------------------------------------------------------------------------
__device__ __forceinline__ uint32_t smem_u32(const void* p) {
    uint32_t a;
    asm("{ .reg .u64 t; cvta.to.shared.u64 t, %1; cvt.u32.u64 %0, t; }"
        : "=r"(a) : "l"(p));
    return a;
}

__device__ __forceinline__ void mma_bf16(float c[4], const uint32_t a[4],
                                         const uint32_t b[2]) {
    asm volatile(
        "mma.sync.aligned.m16n8k16.row.col.f32.bf16.bf16.f32 "
        "{%0,%1,%2,%3},{%4,%5,%6,%7},{%8,%9},{%0,%1,%2,%3};"
        : "+f"(c[0]), "+f"(c[1]), "+f"(c[2]), "+f"(c[3])
        : "r"(a[0]), "r"(a[1]), "r"(a[2]), "r"(a[3]), "r"(b[0]), "r"(b[1]));
}

__device__ __forceinline__ void mma_f16(float c[4], const uint32_t a[4],
                                        const uint32_t b[2]) {
    asm volatile(
        "mma.sync.aligned.m16n8k16.row.col.f32.f16.f16.f32 "
        "{%0,%1,%2,%3},{%4,%5,%6,%7},{%8,%9},{%0,%1,%2,%3};"
        : "+f"(c[0]), "+f"(c[1]), "+f"(c[2]), "+f"(c[3])
        : "r"(a[0]), "r"(a[1]), "r"(a[2]), "r"(a[3]), "r"(b[0]), "r"(b[1]));
}

__device__ __forceinline__ void ldsm4(uint32_t r[4], const void* p) {
    uint32_t a = smem_u32(p);
    asm volatile("ldmatrix.sync.aligned.m8n8.x4.shared.b16 {%0,%1,%2,%3},[%4];"
                 : "=r"(r[0]), "=r"(r[1]), "=r"(r[2]), "=r"(r[3])
                 : "r"(a));
}

__device__ __forceinline__ void cpa16(uint32_t s, const void* g) {
    asm volatile("cp.async.cg.shared.global [%0],[%1],16;" ::"r"(s), "l"(g));
}

__device__ __forceinline__ float ex2f(float x) {
    float r;
    asm("ex2.approx.ftz.f32 %0,%1;" : "=f"(r) : "f"(x));
    return r;
}

// Split two floats into packed bf16 hi/lo pairs
__device__ __forceinline__ void split2(float x, float y, uint32_t& hi, uint32_t& lo) {
    __nv_bfloat16 xh = __float2bfloat16(x);
    __nv_bfloat16 yh = __float2bfloat16(y);
    float xr = x - __bfloat162float(xh);
    float yr = y - __bfloat162float(yh);
    __nv_bfloat162 h2, l2;
    h2.x = xh; h2.y = yh;
    l2.x = __float2bfloat16(xr); l2.y = __float2bfloat16(yr);
    hi = *reinterpret_cast<uint32_t*>(&h2);
    lo = *reinterpret_cast<uint32_t*>(&l2);
}

// Split two floats into packed fp16 hi/lo pairs
__device__ __forceinline__ void split2h(float x, float y, uint32_t& hi, uint32_t& lo) {
    __half xh = __float2half_rn(x);
    __half yh = __float2half_rn(y);
    float xr = x - __half2float(xh);
    float yr = y - __half2float(yh);
    __half2 h2, l2;
    h2.x = xh; h2.y = yh;
    l2.x = __float2half_rn(xr); l2.y = __float2half_rn(yr);
    hi = *reinterpret_cast<uint32_t*>(&h2);
    lo = *reinterpret_cast<uint32_t*>(&l2);
}

// ---------------------------------------------------------------------------
// 1) Elementwise split of x -> bf16 hi/lo
// ---------------------------------------------------------------------------
__global__ void split_x_kernel(const float4* __restrict__ X,
                               __nv_bfloat16* __restrict__ Xh,
                               __nv_bfloat16* __restrict__ Xl, int n4) {
    int i = blockIdx.x * blockDim.x + threadIdx.x;
    if (i >= n4) return;
    float4 v = X[i];
    uint32_t h0, l0, h1, l1;
    split2(v.x, v.y, h0, l0);
    split2(v.z, v.w, h1, l1);
    *(uint32_t*)(Xh + (size_t)i * 4)     = h0;
    *(uint32_t*)(Xh + (size_t)i * 4 + 2) = h1;
    *(uint32_t*)(Xl + (size_t)i * 4)     = l0;
    *(uint32_t*)(Xl + (size_t)i * 4 + 2) = l1;
}

// ---------------------------------------------------------------------------
// 2) Transpose + split W[K,N] -> Wt hi/lo [N,K]
// ---------------------------------------------------------------------------
__global__ void transpose_split_kernel(const float* __restrict__ W,
                                       __nv_bfloat16* __restrict__ Th,
                                       __nv_bfloat16* __restrict__ Tl,
                                       int K, int N) {
    __shared__ float t[32][33];
    int k0 = blockIdx.y * 32, n0 = blockIdx.x * 32;
    int tx = threadIdx.x & 31, ty = threadIdx.x >> 5;
#pragma unroll
    for (int i = 0; i < 4; i++)
        t[ty + 8 * i][tx] = W[(size_t)(k0 + ty + 8 * i) * N + n0 + tx];
    __syncthreads();
#pragma unroll
    for (int i = 0; i < 4; i++) {
        float v = t[tx][ty + 8 * i];
        __nv_bfloat16 hi = __float2bfloat16(v);
        Th[(size_t)(n0 + ty + 8 * i) * K + k0 + tx] = hi;
        Tl[(size_t)(n0 + ty + 8 * i) * K + k0 + tx] =
            __float2bfloat16(v - __bfloat162float(hi));
    }
}

// ---------------------------------------------------------------------------
// 3) Split-bf16 MMA GEMM, BK=32, 2-stage cp.async, 1 sync/iter.
//    C[M,N] = (Ah+Al)[M,K] @ (Bh+Bl)[N,K]^T + bias
// ---------------------------------------------------------------------------
#define G_ROWE  40                    // row stride in bf16 elems (32 + 8 pad)
#define G_ARR   (128 * G_ROWE * 2)    // 10240 B per array
#define G_STAGE (4 * G_ARR)           // 40960 B per stage
#define G_DYN   (2 * G_STAGE)         // 81920 B

__global__ __launch_bounds__(256)
void gemm_split_kernel(const __nv_bfloat16* __restrict__ Ah,
                       const __nv_bfloat16* __restrict__ Al,
                       const __nv_bfloat16* __restrict__ Bh,
                       const __nv_bfloat16* __restrict__ Bl,
                       const float* __restrict__ bias,
                       float* __restrict__ C, int M, int N, int K) {
    extern __shared__ __align__(16) uint8_t dyn[];
    const int tid = threadIdx.x, lane = tid & 31, w = tid >> 5;
    const int wm = w >> 2, wn = w & 3;     // 2 x 4 warp grid
    const int brow = blockIdx.y * 128, bcol = blockIdx.x * 128;
    const uint32_t dbase = smem_u32(dyn);

    float c[4][4][4] = {};

    auto load_stage = [&](int s, int k0) {
        const __nv_bfloat16* ptrs[4] = {
            Ah + (size_t)brow * K, Al + (size_t)brow * K,
            Bh + (size_t)bcol * K, Bl + (size_t)bcol * K};
#pragma unroll
        for (int i = 0; i < 8; i++) {
            int ch = tid + i * 256;        // 0..2047
            int arr = ch >> 9;
            int rem = ch & 511;
            int r = rem >> 2, cc = rem & 3;
            cpa16(dbase + s * G_STAGE + arr * G_ARR + r * (G_ROWE * 2) + cc * 16,
                  ptrs[arr] + (size_t)r * K + k0 + cc * 8);
        }
        asm volatile("cp.async.commit_group;");
    };

    const int NIT = K >> 5;
    load_stage(0, 0);

    for (int it = 0; it < NIT; ++it) {
        const int s = it & 1;
        asm volatile("cp.async.wait_group 0;");
        __syncthreads();
        if (it + 1 < NIT) load_stage(s ^ 1, (it + 1) * 32);

        const __nv_bfloat16* A_h = (const __nv_bfloat16*)(dyn + s * G_STAGE);
        const __nv_bfloat16* A_l = (const __nv_bfloat16*)(dyn + s * G_STAGE + G_ARR);
        const __nv_bfloat16* B_h = (const __nv_bfloat16*)(dyn + s * G_STAGE + 2 * G_ARR);
        const __nv_bfloat16* B_l = (const __nv_bfloat16*)(dyn + s * G_STAGE + 3 * G_ARR);

#pragma unroll
        for (int ks = 0; ks < 2; ks++) {
            const int colb = ks * 16 + (lane >> 4) * 8;
            uint32_t ah[4][4], al[4][4];
#pragma unroll
            for (int mt = 0; mt < 4; mt++) {
                int row = wm * 64 + mt * 16 + (lane & 15);
                ldsm4(ah[mt], A_h + row * G_ROWE + colb);
                ldsm4(al[mt], A_l + row * G_ROWE + colb);
            }
            uint32_t bh[4][2], bl[4][2];
#pragma unroll
            for (int p = 0; p < 2; p++) {
                int row = wn * 32 + p * 16 + (lane & 15);
                uint32_t t[4];
                ldsm4(t, B_h + row * G_ROWE + colb);
                bh[2 * p][0] = t[0]; bh[2 * p][1] = t[2];
                bh[2 * p + 1][0] = t[1]; bh[2 * p + 1][1] = t[3];
                ldsm4(t, B_l + row * G_ROWE + colb);
                bl[2 * p][0] = t[0]; bl[2 * p][1] = t[2];
                bl[2 * p + 1][0] = t[1]; bl[2 * p + 1][1] = t[3];
            }
#pragma unroll
            for (int mt = 0; mt < 4; mt++)
#pragma unroll
                for (int nt = 0; nt < 4; nt++) {
                    mma_bf16(c[mt][nt], ah[mt], bh[nt]);
                    mma_bf16(c[mt][nt], ah[mt], bl[nt]);
                    mma_bf16(c[mt][nt], al[mt], bh[nt]);
                }
        }
    }

    // Epilogue with bias
#pragma unroll
    for (int mt = 0; mt < 4; mt++) {
        int r0 = brow + wm * 64 + mt * 16 + (lane >> 2);
#pragma unroll
        for (int nt = 0; nt < 4; nt++) {
            int col = bcol + wn * 32 + nt * 8 + 2 * (lane & 3);
            float b0 = bias[col], b1 = bias[col + 1];
            float2 v0 = {c[mt][nt][0] + b0, c[mt][nt][1] + b1};
            float2 v1 = {c[mt][nt][2] + b0, c[mt][nt][3] + b1};
            *(float2*)(C + (size_t)r0 * N + col) = v0;
            *(float2*)(C + (size_t)(r0 + 8) * N + col) = v1;
        }
    }
}

// ---------------------------------------------------------------------------
// 4) Repack qkv fp32 -> per-head Q(scaled)/K fp16 [BH,N,64], V^T fp16 hi/lo
// ---------------------------------------------------------------------------
__global__ __launch_bounds__(256)
void repack_kernel(const float* __restrict__ qkv,
                   __half* __restrict__ Qf, __half* __restrict__ Kf,
                   __half* __restrict__ Vth, __half* __restrict__ Vtl) {
    __shared__ float vt[64][65];
    const int bh = blockIdx.y;
    const int b = bh >> 4, h = bh & 15;
    const int nb = blockIdx.x * 64;
    const float qscale = 0.125f * 1.4426950408889634f;  // scale * log2(e)

    for (int idx = threadIdx.x; idx < 64 * 192; idx += 256) {
        int r = idx / 192, cc = idx % 192;
        float v = qkv[(size_t)(b * N_ + nb + r) * QKV_N + h * 192 + cc];
        if (cc < 64) {
            Qf[((size_t)bh * N_ + nb + r) * 64 + cc] = __float2half_rn(v * qscale);
        } else if (cc < 128) {
            Kf[((size_t)bh * N_ + nb + r) * 64 + (cc - 64)] = __float2half_rn(v);
        } else {
            vt[cc - 128][r] = v;
        }
    }
    __syncthreads();
    for (int idx = threadIdx.x; idx < 64 * 64; idx += 256) {
        int d = idx >> 6, nl = idx & 63;
        float v = vt[d][nl];
        __half hi = __float2half_rn(v);
        size_t o = ((size_t)bh * 64 + d) * N_ + nb + nl;
        Vth[o] = hi;
        Vtl[o] = __float2half_rn(v - __half2float(hi));
    }
}

// ---------------------------------------------------------------------------
// 5) FA2 attention: fp16 QK single-term, fp16 PV 3-term.
//    8 warps x 16 q = 128 q/CTA; 64-key tiles, 2-stage cp.async.
// ---------------------------------------------------------------------------
#define A_ROWE  72                    // row stride in half elems (64 + 8 pad)
#define A_ARR   (64 * A_ROWE * 2)     // 9216 B per array (K / Vh / Vl)
#define A_STAGE (3 * A_ARR)           // 27648 B per stage
#define A_DYN   (2 * A_STAGE)         // 55296 B

__global__ __launch_bounds__(256)
void attn_kernel(const __half* __restrict__ Qf, const __half* __restrict__ Kf,
                 const __half* __restrict__ Vth, const __half* __restrict__ Vtl,
                 __nv_bfloat16* __restrict__ Oh, __nv_bfloat16* __restrict__ Ol) {
    extern __shared__ __align__(16) uint8_t dyn[];
    const int tid = threadIdx.x, lane = tid & 31, w = tid >> 5;
    const int bh = blockIdx.y, qb = blockIdx.x;
    const size_t qkbase = (size_t)bh * N_ * 64;
    const size_t vbase = (size_t)bh * 64 * N_;
    const uint32_t abase = smem_u32(dyn);

    // Q fragments (fp16, pre-scaled) held in registers
    uint32_t qh[4][4];
    {
        int r0 = qb * 128 + w * 16 + (lane >> 2);
        int c0 = 2 * (lane & 3);
#pragma unroll
        for (int kd = 0; kd < 4; kd++) {
            const __half* ph = Qf + qkbase + (size_t)r0 * 64 + kd * 16 + c0;
            qh[kd][0] = *(const uint32_t*)(ph);
            qh[kd][1] = *(const uint32_t*)(ph + 8 * 64);
            qh[kd][2] = *(const uint32_t*)(ph + 8);
            qh[kd][3] = *(const uint32_t*)(ph + 8 * 64 + 8);
        }
    }

    auto load_tile = [&](int s, int kt0) {
#pragma unroll
        for (int i = 0; i < 6; i++) {
            int ch = tid + i * 256;        // 0..1535
            int arr = ch >> 9;
            int rem = ch & 511;
            int r = rem >> 3, cc = rem & 7;
            uint32_t dst = abase + s * A_STAGE + arr * A_ARR + r * (A_ROWE * 2) + cc * 16;
            const __half* src;
            if (arr == 0)      src = Kf + qkbase + (size_t)(kt0 + r) * 64 + cc * 8;
            else if (arr == 1) src = Vth + vbase + (size_t)r * N_ + kt0 + cc * 8;
            else               src = Vtl + vbase + (size_t)r * N_ + kt0 + cc * 8;
            cpa16(dst, src);
        }
        asm volatile("cp.async.commit_group;");
    };

    float m0 = -1e30f, m1 = -1e30f, l0 = 0.f, l1 = 0.f;
    float o[8][4] = {};

    const int NT = N_ / 64;
    load_tile(0, 0);

    for (int t = 0; t < NT; ++t) {
        const int s = t & 1;
        asm volatile("cp.async.wait_group 0;");
        __syncthreads();
        if (t + 1 < NT) load_tile(s ^ 1, (t + 1) * 64);

        const __half* ks_ = (const __half*)(dyn + s * A_STAGE);
        const __half* vh_ = (const __half*)(dyn + s * A_STAGE + A_ARR);
        const __half* vl_ = (const __half*)(dyn + s * A_STAGE + 2 * A_ARR);

        // S = Q K^T (single fp16 term, pre-scaled log2 domain)
        float sc[8][4] = {};
#pragma unroll
        for (int kd = 0; kd < 4; kd++) {
            const int colb = kd * 16 + (lane >> 4) * 8;
            uint32_t kb[8][2];
#pragma unroll
            for (int p = 0; p < 4; p++) {
                int row = p * 16 + (lane & 15);
                uint32_t tt[4];
                ldsm4(tt, ks_ + row * A_ROWE + colb);
                kb[2 * p][0] = tt[0]; kb[2 * p][1] = tt[2];
                kb[2 * p + 1][0] = tt[1]; kb[2 * p + 1][1] = tt[3];
            }
#pragma unroll
            for (int nt = 0; nt < 8; nt++)
                mma_f16(sc[nt], qh[kd], kb[nt]);
        }

        // Online softmax (base-2)
        float mx0 = -1e30f, mx1 = -1e30f;
#pragma unroll
        for (int nt = 0; nt < 8; nt++) {
            mx0 = fmaxf(mx0, fmaxf(sc[nt][0], sc[nt][1]));
            mx1 = fmaxf(mx1, fmaxf(sc[nt][2], sc[nt][3]));
        }
        mx0 = fmaxf(mx0, __shfl_xor_sync(0xffffffffu, mx0, 1));
        mx0 = fmaxf(mx0, __shfl_xor_sync(0xffffffffu, mx0, 2));
        mx1 = fmaxf(mx1, __shfl_xor_sync(0xffffffffu, mx1, 1));
        mx1 = fmaxf(mx1, __shfl_xor_sync(0xffffffffu, mx1, 2));
        float mn0 = fmaxf(m0, mx0), mn1 = fmaxf(m1, mx1);
        float a0 = ex2f(m0 - mn0), a1 = ex2f(m1 - mn1);
        m0 = mn0; m1 = mn1;

        float sum0 = 0.f, sum1 = 0.f;
#pragma unroll
        for (int nt = 0; nt < 8; nt++) {
            sc[nt][0] = ex2f(sc[nt][0] - mn0);
            sc[nt][1] = ex2f(sc[nt][1] - mn0);
            sc[nt][2] = ex2f(sc[nt][2] - mn1);
            sc[nt][3] = ex2f(sc[nt][3] - mn1);
            sum0 += sc[nt][0] + sc[nt][1];
            sum1 += sc[nt][2] + sc[nt][3];
        }
        sum0 += __shfl_xor_sync(0xffffffffu, sum0, 1);
        sum0 += __shfl_xor_sync(0xffffffffu, sum0, 2);
        sum1 += __shfl_xor_sync(0xffffffffu, sum1, 1);
        sum1 += __shfl_xor_sync(0xffffffffu, sum1, 2);
        l0 = l0 * a0 + sum0;
        l1 = l1 * a1 + sum1;
#pragma unroll
        for (int nd = 0; nd < 8; nd++) {
            o[nd][0] *= a0; o[nd][1] *= a0;
            o[nd][2] *= a1; o[nd][3] *= a1;
        }

        // P fragments, fp16 hi/lo
        uint32_t pah[4][4], pal[4][4];
#pragma unroll
        for (int kt = 0; kt < 4; kt++) {
            split2h(sc[2 * kt][0], sc[2 * kt][1], pah[kt][0], pal[kt][0]);
            split2h(sc[2 * kt][2], sc[2 * kt][3], pah[kt][1], pal[kt][1]);
            split2h(sc[2 * kt + 1][0], sc[2 * kt + 1][1], pah[kt][2], pal[kt][2]);
            split2h(sc[2 * kt + 1][2], sc[2 * kt + 1][3], pah[kt][3], pal[kt][3]);
        }

        // O += P V (3-term fp16)
#pragma unroll
        for (int kt = 0; kt < 4; kt++) {
            const int colb = kt * 16 + (lane >> 4) * 8;
            uint32_t vbh[8][2], vbl[8][2];
#pragma unroll
            for (int p = 0; p < 4; p++) {
                int row = p * 16 + (lane & 15);
                uint32_t tt[4];
                ldsm4(tt, vh_ + row * A_ROWE + colb);
                vbh[2 * p][0] = tt[0]; vbh[2 * p][1] = tt[2];
                vbh[2 * p + 1][0] = tt[1]; vbh[2 * p + 1][1] = tt[3];
                ldsm4(tt, vl_ + row * A_ROWE + colb);
                vbl[2 * p][0] = tt[0]; vbl[2 * p][1] = tt[2];
                vbl[2 * p + 1][0] = tt[1]; vbl[2 * p + 1][1] = tt[3];
            }
#pragma unroll
            for (int nd = 0; nd < 8; nd++) {
                mma_f16(o[nd], pah[kt], vbh[nd]);
                mma_f16(o[nd], pah[kt], vbl[nd]);
                mma_f16(o[nd], pal[kt], vbh[nd]);
            }
        }
    }

    // Epilogue: normalize, split to bf16 hi/lo for out-projection
    float i0 = 1.f / l0, i1 = 1.f / l1;
    int b = bh >> 4, h = bh & 15;
    int r0 = b * N_ + qb * 128 + w * 16 + (lane >> 2);
#pragma unroll
    for (int nd = 0; nd < 8; nd++) {
        int col = h * 64 + nd * 8 + 2 * (lane & 3);
        uint32_t hi, lo;
        split2(o[nd][0] * i0, o[nd][1] * i0, hi, lo);
        *(uint32_t*)(Oh + (size_t)r0 * E_ + col) = hi;
        *(uint32_t*)(Ol + (size_t)r0 * E_ + col) = lo;
        split2(o[nd][2] * i1, o[nd][3] * i1, hi, lo);
        *(uint32_t*)(Oh + (size_t)(r0 + 8) * E_ + col) = hi;
        *(uint32_t*)(Ol + (size_t)(r0 + 8) * E_ + col) = lo;
    }
}

// ---------------------------------------------------------------------------
extern "C" void kernel_launch(void* const* d_in, const int* in_sizes, int n_in,
                              void* d_out, int out_size) {
    (void)in_sizes; (void)n_in; (void)out_size;
    const float* x     = (const float*)d_in[0];
    const float* W_qkv = (const float*)d_in[1];
    const float* b_qkv = (const float*)d_in[2];
    const float* W_out = (const float*)d_in[3];
    const float* b_out = (const float*)d_in[4];
    float* out = (float*)d_out;

    __nv_bfloat16 *wqh, *wql, *woh, *wol, *xh, *xl, *o_h, *o_l;
    __half *q_f, *k_f, *vt_h, *vt_l;
    float* qkv;
    cudaGetSymbolAddress((void**)&wqh, g_wqkv_h);
    cudaGetSymbolAddress((void**)&wql, g_wqkv_l);
    cudaGetSymbolAddress((void**)&woh, g_wout_h);
    cudaGetSymbolAddress((void**)&wol, g_wout_l);
    cudaGetSymbolAddress((void**)&xh, g_xh);
    cudaGetSymbolAddress((void**)&xl, g_xl);
    cudaGetSymbolAddress((void**)&qkv, g_qkv);
    cudaGetSymbolAddress((void**)&q_f, g_qf);
    cudaGetSymbolAddress((void**)&k_f, g_kf);
    cudaGetSymbolAddress((void**)&vt_h, g_vth);
    cudaGetSymbolAddress((void**)&vt_l, g_vtl);
    cudaGetSymbolAddress((void**)&o_h, g_oh);
    cudaGetSymbolAddress((void**)&o_l, g_ol);

    // Dynamic-smem limits (host-side attribute set; no-op on replay)
    cudaFuncSetAttribute(gemm_split_kernel,
                         cudaFuncAttributeMaxDynamicSharedMemorySize, G_DYN);
    cudaFuncSetAttribute(attn_kernel,
                         cudaFuncAttributeMaxDynamicSharedMemorySize, A_DYN);

    // Prep: split x, transpose+split weights
    split_x_kernel<<<(M_TOT * E_ / 4 + 255) / 256, 256>>>((const float4*)x, xh, xl,
                                                          M_TOT * E_ / 4);
    transpose_split_kernel<<<dim3(QKV_N / 32, E_ / 32), 256>>>(W_qkv, wqh, wql, E_, QKV_N);
    transpose_split_kernel<<<dim3(E_ / 32, E_ / 32), 256>>>(W_out, woh, wol, E_, E_);

    // QKV projection
    gemm_split_kernel<<<dim3(QKV_N / 128, M_TOT / 128), 256, G_DYN>>>(
        xh, xl, wqh, wql, b_qkv, qkv, M_TOT, QKV_N, E_);

    // Repack into per-head fp16 layouts
    repack_kernel<<<dim3(N_ / 64, BH_), 256>>>(qkv, q_f, k_f, vt_h, vt_l);

    // Attention
    attn_kernel<<<dim3(N_ / 128, BH_), 256, A_DYN>>>(q_f, k_f, vt_h, vt_l, o_h, o_l);

    // Output projection
    gemm_split_kernel<<<dim3(E_ / 128, M_TOT / 128), 256, G_DYN>>>(
        o_h, o_l, woh, wol, b_out, out, M_TOT, E_, E_);
}

// round 8
// speedup vs baseline: 1.7036x; 1.3741x over previous
#include <cuda_runtime.h>
#include <cuda_bf16.h>
#include <cuda_fp16.h>
#include <stdint.h>

// Problem constants
#define B_   2
#define N_   2048
#define E_   1024
#define H_   16
#define HD_  64
#define M_TOT  (B_ * N_)     // 4096
#define QKV_N  (3 * E_)      // 3072
#define BH_    (B_ * H_)     // 32

// ---------------------------------------------------------------------------
// Device scratch (allocation-free rule)
// ---------------------------------------------------------------------------
__device__ __nv_bfloat16 g_wqkv_h[(size_t)QKV_N * E_];
__device__ __nv_bfloat16 g_wqkv_l[(size_t)QKV_N * E_];
__device__ __nv_bfloat16 g_wout_h[(size_t)E_ * E_];
__device__ __nv_bfloat16 g_wout_l[(size_t)E_ * E_];
__device__ __nv_bfloat16 g_xh[(size_t)M_TOT * E_];
__device__ __nv_bfloat16 g_xl[(size_t)M_TOT * E_];
__device__ float g_qkv[(size_t)M_TOT * QKV_N];
__device__ __half g_qf[(size_t)BH_ * N_ * HD_];
__device__ __half g_kf[(size_t)BH_ * N_ * HD_];
__device__ __half g_vth[(size_t)BH_ * HD_ * N_];
__device__ __half g_vtl[(size_t)BH_ * HD_ * N_];
__device__ __nv_bfloat16 g_oh[(size_t)M_TOT * E_];
__device__ __nv_bfloat16 g_ol[(size_t)M_TOT * E_];

// ---------------------------------------------------------------------------
// Helpers
// ---------------------------------------------------------------------------
__device__ __forceinline__ uint32_t smem_u32(const void* p) {
    uint32_t a;
    asm("{ .reg .u64 t; cvta.to.shared.u64 t, %1; cvt.u32.u64 %0, t; }"
        : "=r"(a) : "l"(p));
    return a;
}

__device__ __forceinline__ void mma_bf16(float c[4], const uint32_t a[4],
                                         const uint32_t b[2]) {
    asm volatile(
        "mma.sync.aligned.m16n8k16.row.col.f32.bf16.bf16.f32 "
        "{%0,%1,%2,%3},{%4,%5,%6,%7},{%8,%9},{%0,%1,%2,%3};"
        : "+f"(c[0]), "+f"(c[1]), "+f"(c[2]), "+f"(c[3])
        : "r"(a[0]), "r"(a[1]), "r"(a[2]), "r"(a[3]), "r"(b[0]), "r"(b[1]));
}

__device__ __forceinline__ void mma_f16(float c[4], const uint32_t a[4],
                                        const uint32_t b[2]) {
    asm volatile(
        "mma.sync.aligned.m16n8k16.row.col.f32.f16.f16.f32 "
        "{%0,%1,%2,%3},{%4,%5,%6,%7},{%8,%9},{%0,%1,%2,%3};"
        : "+f"(c[0]), "+f"(c[1]), "+f"(c[2]), "+f"(c[3])
        : "r"(a[0]), "r"(a[1]), "r"(a[2]), "r"(a[3]), "r"(b[0]), "r"(b[1]));
}

__device__ __forceinline__ void ldsm4(uint32_t r[4], const void* p) {
    uint32_t a = smem_u32(p);
    asm volatile("ldmatrix.sync.aligned.m8n8.x4.shared.b16 {%0,%1,%2,%3},[%4];"
                 : "=r"(r[0]), "=r"(r[1]), "=r"(r[2]), "=r"(r[3])
                 : "r"(a));
}

__device__ __forceinline__ void cpa16(uint32_t s, const void* g) {
    asm volatile("cp.async.cg.shared.global [%0],[%1],16;" ::"r"(s), "l"(g));
}

__device__ __forceinline__ float ex2f(float x) {
    float r;
    asm("ex2.approx.ftz.f32 %0,%1;" : "=f"(r) : "f"(x));
    return r;
}

// Split two floats into packed bf16 hi/lo pairs
__device__ __forceinline__ void split2(float x, float y, uint32_t& hi, uint32_t& lo) {
    __nv_bfloat16 xh = __float2bfloat16(x);
    __nv_bfloat16 yh = __float2bfloat16(y);
    float xr = x - __bfloat162float(xh);
    float yr = y - __bfloat162float(yh);
    __nv_bfloat162 h2, l2;
    h2.x = xh; h2.y = yh;
    l2.x = __float2bfloat16(xr); l2.y = __float2bfloat16(yr);
    hi = *reinterpret_cast<uint32_t*>(&h2);
    lo = *reinterpret_cast<uint32_t*>(&l2);
}

// Split two floats into packed fp16 hi/lo pairs
__device__ __forceinline__ void split2h(float x, float y, uint32_t& hi, uint32_t& lo) {
    __half xh = __float2half_rn(x);
    __half yh = __float2half_rn(y);
    float xr = x - __half2float(xh);
    float yr = y - __half2float(yh);
    __half2 h2, l2;
    h2.x = xh; h2.y = yh;
    l2.x = __float2half_rn(xr); l2.y = __float2half_rn(yr);
    hi = *reinterpret_cast<uint32_t*>(&h2);
    lo = *reinterpret_cast<uint32_t*>(&l2);
}

// ---------------------------------------------------------------------------
// 1) Elementwise split of x -> bf16 hi/lo
// ---------------------------------------------------------------------------
__global__ void split_x_kernel(const float4* __restrict__ X,
                               __nv_bfloat16* __restrict__ Xh,
                               __nv_bfloat16* __restrict__ Xl, int n4) {
    int i = blockIdx.x * blockDim.x + threadIdx.x;
    if (i >= n4) return;
    float4 v = X[i];
    uint32_t h0, l0, h1, l1;
    split2(v.x, v.y, h0, l0);
    split2(v.z, v.w, h1, l1);
    *(uint32_t*)(Xh + (size_t)i * 4)     = h0;
    *(uint32_t*)(Xh + (size_t)i * 4 + 2) = h1;
    *(uint32_t*)(Xl + (size_t)i * 4)     = l0;
    *(uint32_t*)(Xl + (size_t)i * 4 + 2) = l1;
}

// ---------------------------------------------------------------------------
// 2) Transpose + split W[K,N] -> Wt hi/lo [N,K]
// ---------------------------------------------------------------------------
__global__ void transpose_split_kernel(const float* __restrict__ W,
                                       __nv_bfloat16* __restrict__ Th,
                                       __nv_bfloat16* __restrict__ Tl,
                                       int K, int N) {
    __shared__ float t[32][33];
    int k0 = blockIdx.y * 32, n0 = blockIdx.x * 32;
    int tx = threadIdx.x & 31, ty = threadIdx.x >> 5;
#pragma unroll
    for (int i = 0; i < 4; i++)
        t[ty + 8 * i][tx] = W[(size_t)(k0 + ty + 8 * i) * N + n0 + tx];
    __syncthreads();
#pragma unroll
    for (int i = 0; i < 4; i++) {
        float v = t[tx][ty + 8 * i];
        __nv_bfloat16 hi = __float2bfloat16(v);
        Th[(size_t)(n0 + ty + 8 * i) * K + k0 + tx] = hi;
        Tl[(size_t)(n0 + ty + 8 * i) * K + k0 + tx] =
            __float2bfloat16(v - __bfloat162float(hi));
    }
}

// ---------------------------------------------------------------------------
// 3) Split-bf16 MMA GEMM (EXACT R2 version, measured 337us on QKV):
//    BM=BN=128, BK=16, 256 thr, 2-stage cp.async pipeline.
// ---------------------------------------------------------------------------
__global__ __launch_bounds__(256)
void gemm_split_kernel(const __nv_bfloat16* __restrict__ Ah,
                       const __nv_bfloat16* __restrict__ Al,
                       const __nv_bfloat16* __restrict__ Bh,
                       const __nv_bfloat16* __restrict__ Bl,
                       const float* __restrict__ bias,
                       float* __restrict__ C, int M, int N, int K) {
    __shared__ __nv_bfloat16 sm[2][4][128][24];  // 48KB; arr: Ah,Al,Bh,Bl
    const int tid = threadIdx.x, lane = tid & 31, w = tid >> 5;
    const int wm = w >> 2, wn = w & 3;           // 2 x 4 warp grid
    const int brow = blockIdx.y * 128, bcol = blockIdx.x * 128;

    float c[4][4][4] = {};

    auto load_stage = [&](int s, int k0) {
#pragma unroll
        for (int i = 0; i < 4; i++) {
            int ch = tid + i * 256;   // 0..1023
            int arr = ch >> 8;
            int r = (ch & 255) >> 1;
            int h8 = (ch & 1) * 8;
            const __nv_bfloat16* g;
            if (arr == 0)      g = Ah + (size_t)(brow + r) * K + k0 + h8;
            else if (arr == 1) g = Al + (size_t)(brow + r) * K + k0 + h8;
            else if (arr == 2) g = Bh + (size_t)(bcol + r) * K + k0 + h8;
            else               g = Bl + (size_t)(bcol + r) * K + k0 + h8;
            cpa16(smem_u32(&sm[s][arr][r][h8]), g);
        }
        asm volatile("cp.async.commit_group;");
    };

    const int NIT = K >> 4;
    load_stage(0, 0);
    for (int it = 0; it < NIT; ++it) {
        if (it + 1 < NIT) {
            load_stage((it + 1) & 1, (it + 1) * 16);
            asm volatile("cp.async.wait_group 1;");
        } else {
            asm volatile("cp.async.wait_group 0;");
        }
        __syncthreads();
        int s = it & 1;
        uint32_t ah[4][4], al[4][4];
#pragma unroll
        for (int mt = 0; mt < 4; mt++) {
            int row = wm * 64 + mt * 16 + (lane & 15);
            int col = (lane >> 4) * 8;
            ldsm4(ah[mt], &sm[s][0][row][col]);
            ldsm4(al[mt], &sm[s][1][row][col]);
        }
        uint32_t bh[4][2], bl[4][2];
#pragma unroll
        for (int p = 0; p < 2; p++) {
            int row = wn * 32 + p * 16 + (lane & 15);
            int col = (lane >> 4) * 8;
            uint32_t t[4];
            ldsm4(t, &sm[s][2][row][col]);
            bh[2 * p][0] = t[0]; bh[2 * p][1] = t[2];
            bh[2 * p + 1][0] = t[1]; bh[2 * p + 1][1] = t[3];
            ldsm4(t, &sm[s][3][row][col]);
            bl[2 * p][0] = t[0]; bl[2 * p][1] = t[2];
            bl[2 * p + 1][0] = t[1]; bl[2 * p + 1][1] = t[3];
        }
#pragma unroll
        for (int mt = 0; mt < 4; mt++)
#pragma unroll
            for (int nt = 0; nt < 4; nt++) {
                mma_bf16(c[mt][nt], ah[mt], bh[nt]);
                mma_bf16(c[mt][nt], ah[mt], bl[nt]);
                mma_bf16(c[mt][nt], al[mt], bh[nt]);
            }
        __syncthreads();
    }

    // Epilogue with bias
#pragma unroll
    for (int mt = 0; mt < 4; mt++) {
        int r0 = brow + wm * 64 + mt * 16 + (lane >> 2);
#pragma unroll
        for (int nt = 0; nt < 4; nt++) {
            int col = bcol + wn * 32 + nt * 8 + 2 * (lane & 3);
            float b0 = bias[col], b1 = bias[col + 1];
            float2 v0 = {c[mt][nt][0] + b0, c[mt][nt][1] + b1};
            float2 v1 = {c[mt][nt][2] + b0, c[mt][nt][3] + b1};
            *(float2*)(C + (size_t)r0 * N + col) = v0;
            *(float2*)(C + (size_t)(r0 + 8) * N + col) = v1;
        }
    }
}

// ---------------------------------------------------------------------------
// 4) Repack qkv fp32 -> per-head Q(scaled)/K fp16 [BH,N,64], V^T fp16 hi/lo
// ---------------------------------------------------------------------------
__global__ __launch_bounds__(256)
void repack_kernel(const float* __restrict__ qkv,
                   __half* __restrict__ Qf, __half* __restrict__ Kf,
                   __half* __restrict__ Vth, __half* __restrict__ Vtl) {
    __shared__ float vt[64][65];
    const int bh = blockIdx.y;
    const int b = bh >> 4, h = bh & 15;
    const int nb = blockIdx.x * 64;
    const float qscale = 0.125f * 1.4426950408889634f;  // scale * log2(e)

    for (int idx = threadIdx.x; idx < 64 * 192; idx += 256) {
        int r = idx / 192, cc = idx % 192;
        float v = qkv[(size_t)(b * N_ + nb + r) * QKV_N + h * 192 + cc];
        if (cc < 64) {
            Qf[((size_t)bh * N_ + nb + r) * 64 + cc] = __float2half_rn(v * qscale);
        } else if (cc < 128) {
            Kf[((size_t)bh * N_ + nb + r) * 64 + (cc - 64)] = __float2half_rn(v);
        } else {
            vt[cc - 128][r] = v;
        }
    }
    __syncthreads();
    for (int idx = threadIdx.x; idx < 64 * 64; idx += 256) {
        int d = idx >> 6, nl = idx & 63;
        float v = vt[d][nl];
        __half hi = __float2half_rn(v);
        size_t o = ((size_t)bh * 64 + d) * N_ + nb + nl;
        Vth[o] = hi;
        Vtl[o] = __float2half_rn(v - __half2float(hi));
    }
}

// ---------------------------------------------------------------------------
// 5) FA2 attention (R2 skeleton, fp16 numerics):
//    single fp16 QK^T term, 3-term fp16 PV. 8 warps x 16 q = 128 q/CTA.
// ---------------------------------------------------------------------------
__global__ __launch_bounds__(256)
void attn_kernel(const __half* __restrict__ Qf, const __half* __restrict__ Kf,
                 const __half* __restrict__ Vth, const __half* __restrict__ Vtl,
                 __nv_bfloat16* __restrict__ Oh, __nv_bfloat16* __restrict__ Ol) {
    __shared__ __half ks[64][72];       // K tile
    __shared__ __half vs[2][64][72];    // V hi/lo, transposed [d][key]
    const int tid = threadIdx.x, lane = tid & 31, w = tid >> 5;
    const int bh = blockIdx.y, qb = blockIdx.x;
    const size_t qkbase = (size_t)bh * N_ * 64;
    const size_t vbase = (size_t)bh * 64 * N_;

    // Q fragments (fp16, pre-scaled) held in registers
    uint32_t qh[4][4];
    {
        int r0 = qb * 128 + w * 16 + (lane >> 2);
        int c0 = 2 * (lane & 3);
#pragma unroll
        for (int kd = 0; kd < 4; kd++) {
            const __half* ph = Qf + qkbase + (size_t)r0 * 64 + kd * 16 + c0;
            qh[kd][0] = *(const uint32_t*)(ph);
            qh[kd][1] = *(const uint32_t*)(ph + 8 * 64);
            qh[kd][2] = *(const uint32_t*)(ph + 8);
            qh[kd][3] = *(const uint32_t*)(ph + 8 * 64 + 8);
        }
    }

    float m0 = -1e30f, m1 = -1e30f, l0 = 0.f, l1 = 0.f;
    float o[8][4] = {};

    for (int kt0 = 0; kt0 < N_; kt0 += 64) {
        __syncthreads();
        // Load K (512 float4) + Vh (512) + Vl (512) = 1536 chunks, 6/thread
#pragma unroll
        for (int i = 0; i < 6; i++) {
            int ch = tid + i * 256;         // 0..1535
            int arr = ch >> 9;
            int rem = ch & 511;
            int r = rem >> 3;
            int h8 = (rem & 7) * 8;
            if (arr == 0)
                *(float4*)&ks[r][h8] = *(const float4*)(Kf + qkbase + (size_t)(kt0 + r) * 64 + h8);
            else if (arr == 1)
                *(float4*)&vs[0][r][h8] = *(const float4*)(Vth + vbase + (size_t)r * N_ + kt0 + h8);
            else
                *(float4*)&vs[1][r][h8] = *(const float4*)(Vtl + vbase + (size_t)r * N_ + kt0 + h8);
        }
        __syncthreads();

        // S = Q K^T (single fp16 term, pre-scaled log2 domain)
        float sc[8][4] = {};
#pragma unroll
        for (int kd = 0; kd < 4; kd++) {
            const int colb = kd * 16 + (lane >> 4) * 8;
            uint32_t kb[8][2];
#pragma unroll
            for (int p = 0; p < 4; p++) {
                int row = p * 16 + (lane & 15);
                uint32_t tt[4];
                ldsm4(tt, &ks[row][colb]);
                kb[2 * p][0] = tt[0]; kb[2 * p][1] = tt[2];
                kb[2 * p + 1][0] = tt[1]; kb[2 * p + 1][1] = tt[3];
            }
#pragma unroll
            for (int nt = 0; nt < 8; nt++)
                mma_f16(sc[nt], qh[kd], kb[nt]);
        }

        // Online softmax (base-2)
        float mx0 = -1e30f, mx1 = -1e30f;
#pragma unroll
        for (int nt = 0; nt < 8; nt++) {
            mx0 = fmaxf(mx0, fmaxf(sc[nt][0], sc[nt][1]));
            mx1 = fmaxf(mx1, fmaxf(sc[nt][2], sc[nt][3]));
        }
        mx0 = fmaxf(mx0, __shfl_xor_sync(0xffffffffu, mx0, 1));
        mx0 = fmaxf(mx0, __shfl_xor_sync(0xffffffffu, mx0, 2));
        mx1 = fmaxf(mx1, __shfl_xor_sync(0xffffffffu, mx1, 1));
        mx1 = fmaxf(mx1, __shfl_xor_sync(0xffffffffu, mx1, 2));
        float mn0 = fmaxf(m0, mx0), mn1 = fmaxf(m1, mx1);
        float a0 = ex2f(m0 - mn0), a1 = ex2f(m1 - mn1);
        m0 = mn0; m1 = mn1;

        float sum0 = 0.f, sum1 = 0.f;
#pragma unroll
        for (int nt = 0; nt < 8; nt++) {
            sc[nt][0] = ex2f(sc[nt][0] - mn0);
            sc[nt][1] = ex2f(sc[nt][1] - mn0);
            sc[nt][2] = ex2f(sc[nt][2] - mn1);
            sc[nt][3] = ex2f(sc[nt][3] - mn1);
            sum0 += sc[nt][0] + sc[nt][1];
            sum1 += sc[nt][2] + sc[nt][3];
        }
        sum0 += __shfl_xor_sync(0xffffffffu, sum0, 1);
        sum0 += __shfl_xor_sync(0xffffffffu, sum0, 2);
        sum1 += __shfl_xor_sync(0xffffffffu, sum1, 1);
        sum1 += __shfl_xor_sync(0xffffffffu, sum1, 2);
        l0 = l0 * a0 + sum0;
        l1 = l1 * a1 + sum1;
#pragma unroll
        for (int nd = 0; nd < 8; nd++) {
            o[nd][0] *= a0; o[nd][1] *= a0;
            o[nd][2] *= a1; o[nd][3] *= a1;
        }

        // P fragments, fp16 hi/lo
        uint32_t pah[4][4], pal[4][4];
#pragma unroll
        for (int kt = 0; kt < 4; kt++) {
            split2h(sc[2 * kt][0], sc[2 * kt][1], pah[kt][0], pal[kt][0]);
            split2h(sc[2 * kt][2], sc[2 * kt][3], pah[kt][1], pal[kt][1]);
            split2h(sc[2 * kt + 1][0], sc[2 * kt + 1][1], pah[kt][2], pal[kt][2]);
            split2h(sc[2 * kt + 1][2], sc[2 * kt + 1][3], pah[kt][3], pal[kt][3]);
        }

        // O += P V (3-term fp16)
#pragma unroll
        for (int kt = 0; kt < 4; kt++) {
            const int colb = kt * 16 + (lane >> 4) * 8;
            uint32_t vbh[8][2], vbl[8][2];
#pragma unroll
            for (int p = 0; p < 4; p++) {
                int row = p * 16 + (lane & 15);
                uint32_t tt[4];
                ldsm4(tt, &vs[0][row][colb]);
                vbh[2 * p][0] = tt[0]; vbh[2 * p][1] = tt[2];
                vbh[2 * p + 1][0] = tt[1]; vbh[2 * p + 1][1] = tt[3];
                ldsm4(tt, &vs[1][row][colb]);
                vbl[2 * p][0] = tt[0]; vbl[2 * p][1] = tt[2];
                vbl[2 * p + 1][0] = tt[1]; vbl[2 * p + 1][1] = tt[3];
            }
#pragma unroll
            for (int nd = 0; nd < 8; nd++) {
                mma_f16(o[nd], pah[kt], vbh[nd]);
                mma_f16(o[nd], pah[kt], vbl[nd]);
                mma_f16(o[nd], pal[kt], vbh[nd]);
            }
        }
    }

    // Epilogue: normalize, split to bf16 hi/lo for out-projection
    float i0 = 1.f / l0, i1 = 1.f / l1;
    int b = bh >> 4, h = bh & 15;
    int r0 = b * N_ + qb * 128 + w * 16 + (lane >> 2);
#pragma unroll
    for (int nd = 0; nd < 8; nd++) {
        int col = h * 64 + nd * 8 + 2 * (lane & 3);
        uint32_t hi, lo;
        split2(o[nd][0] * i0, o[nd][1] * i0, hi, lo);
        *(uint32_t*)(Oh + (size_t)r0 * E_ + col) = hi;
        *(uint32_t*)(Ol + (size_t)r0 * E_ + col) = lo;
        split2(o[nd][2] * i1, o[nd][3] * i1, hi, lo);
        *(uint32_t*)(Oh + (size_t)(r0 + 8) * E_ + col) = hi;
        *(uint32_t*)(Ol + (size_t)(r0 + 8) * E_ + col) = lo;
    }
}

// ---------------------------------------------------------------------------
extern "C" void kernel_launch(void* const* d_in, const int* in_sizes, int n_in,
                              void* d_out, int out_size) {
    (void)in_sizes; (void)n_in; (void)out_size;
    const float* x     = (const float*)d_in[0];
    const float* W_qkv = (const float*)d_in[1];
    const float* b_qkv = (const float*)d_in[2];
    const float* W_out = (const float*)d_in[3];
    const float* b_out = (const float*)d_in[4];
    float* out = (float*)d_out;

    __nv_bfloat16 *wqh, *wql, *woh, *wol, *xh, *xl, *o_h, *o_l;
    __half *q_f, *k_f, *vt_h, *vt_l;
    float* qkv;
    cudaGetSymbolAddress((void**)&wqh, g_wqkv_h);
    cudaGetSymbolAddress((void**)&wql, g_wqkv_l);
    cudaGetSymbolAddress((void**)&woh, g_wout_h);
    cudaGetSymbolAddress((void**)&wol, g_wout_l);
    cudaGetSymbolAddress((void**)&xh, g_xh);
    cudaGetSymbolAddress((void**)&xl, g_xl);
    cudaGetSymbolAddress((void**)&qkv, g_qkv);
    cudaGetSymbolAddress((void**)&q_f, g_qf);
    cudaGetSymbolAddress((void**)&k_f, g_kf);
    cudaGetSymbolAddress((void**)&vt_h, g_vth);
    cudaGetSymbolAddress((void**)&vt_l, g_vtl);
    cudaGetSymbolAddress((void**)&o_h, g_oh);
    cudaGetSymbolAddress((void**)&o_l, g_ol);

    // Prep: split x, transpose+split weights
    split_x_kernel<<<(M_TOT * E_ / 4 + 255) / 256, 256>>>((const float4*)x, xh, xl,
                                                          M_TOT * E_ / 4);
    transpose_split_kernel<<<dim3(QKV_N / 32, E_ / 32), 256>>>(W_qkv, wqh, wql, E_, QKV_N);
    transpose_split_kernel<<<dim3(E_ / 32, E_ / 32), 256>>>(W_out, woh, wol, E_, E_);

    // QKV projection (R2 GEMM)
    gemm_split_kernel<<<dim3(QKV_N / 128, M_TOT / 128), 256>>>(
        xh, xl, wqh, wql, b_qkv, qkv, M_TOT, QKV_N, E_);

    // Repack into per-head fp16 layouts
    repack_kernel<<<dim3(N_ / 64, BH_), 256>>>(qkv, q_f, k_f, vt_h, vt_l);

    // Attention
    attn_kernel<<<dim3(N_ / 128, BH_), 256>>>(q_f, k_f, vt_h, vt_l, o_h, o_l);

    // Output projection (R2 GEMM)
    gemm_split_kernel<<<dim3(E_ / 128, M_TOT / 128), 256>>>(
        o_h, o_l, woh, wol, b_out, out, M_TOT, E_, E_);
}

// round 9
// speedup vs baseline: 2.3048x; 1.3529x over previous
#include <cuda_runtime.h>
#include <cuda_bf16.h>
#include <cuda_fp16.h>
#include <stdint.h>

// Problem constants
#define B_   2
#define N_   2048
#define E_   1024
#define H_   16
#define HD_  64
#define M_TOT  (B_ * N_)     // 4096
#define QKV_N  (3 * E_)      // 3072
#define BH_    (B_ * H_)     // 32

// ---------------------------------------------------------------------------
// Device scratch (allocation-free rule)
// ---------------------------------------------------------------------------
__device__ __half g_wqkv[(size_t)QKV_N * E_];          // fp16 single
__device__ __nv_bfloat16 g_wout_h[(size_t)E_ * E_];
__device__ __nv_bfloat16 g_wout_l[(size_t)E_ * E_];
__device__ __half g_xh[(size_t)M_TOT * E_];
__device__ __half g_xl[(size_t)M_TOT * E_];
__device__ float g_qkv[(size_t)M_TOT * QKV_N];
__device__ __half g_qf[(size_t)BH_ * N_ * HD_];
__device__ __half g_kf[(size_t)BH_ * N_ * HD_];
__device__ __half g_vt[(size_t)BH_ * HD_ * N_];
__device__ __nv_bfloat16 g_oh[(size_t)M_TOT * E_];
__device__ __nv_bfloat16 g_ol[(size_t)M_TOT * E_];

// ---------------------------------------------------------------------------
// Helpers
// ---------------------------------------------------------------------------
__device__ __forceinline__ uint32_t smem_u32(const void* p) {
    uint32_t a;
    asm("{ .reg .u64 t; cvta.to.shared.u64 t, %1; cvt.u32.u64 %0, t; }"
        : "=r"(a) : "l"(p));
    return a;
}

__device__ __forceinline__ void mma_bf16(float c[4], const uint32_t a[4],
                                         const uint32_t b[2]) {
    asm volatile(
        "mma.sync.aligned.m16n8k16.row.col.f32.bf16.bf16.f32 "
        "{%0,%1,%2,%3},{%4,%5,%6,%7},{%8,%9},{%0,%1,%2,%3};"
        : "+f"(c[0]), "+f"(c[1]), "+f"(c[2]), "+f"(c[3])
        : "r"(a[0]), "r"(a[1]), "r"(a[2]), "r"(a[3]), "r"(b[0]), "r"(b[1]));
}

__device__ __forceinline__ void mma_f16(float c[4], const uint32_t a[4],
                                        const uint32_t b[2]) {
    asm volatile(
        "mma.sync.aligned.m16n8k16.row.col.f32.f16.f16.f32 "
        "{%0,%1,%2,%3},{%4,%5,%6,%7},{%8,%9},{%0,%1,%2,%3};"
        : "+f"(c[0]), "+f"(c[1]), "+f"(c[2]), "+f"(c[3])
        : "r"(a[0]), "r"(a[1]), "r"(a[2]), "r"(a[3]), "r"(b[0]), "r"(b[1]));
}

__device__ __forceinline__ void ldsm4(uint32_t r[4], const void* p) {
    uint32_t a = smem_u32(p);
    asm volatile("ldmatrix.sync.aligned.m8n8.x4.shared.b16 {%0,%1,%2,%3},[%4];"
                 : "=r"(r[0]), "=r"(r[1]), "=r"(r[2]), "=r"(r[3])
                 : "r"(a));
}

__device__ __forceinline__ void cpa16(uint32_t s, const void* g) {
    asm volatile("cp.async.cg.shared.global [%0],[%1],16;" ::"r"(s), "l"(g));
}

__device__ __forceinline__ float ex2f(float x) {
    float r;
    asm("ex2.approx.ftz.f32 %0,%1;" : "=f"(r) : "f"(x));
    return r;
}

// Split two floats into packed bf16 hi/lo pairs
__device__ __forceinline__ void split2(float x, float y, uint32_t& hi, uint32_t& lo) {
    __nv_bfloat16 xh = __float2bfloat16(x);
    __nv_bfloat16 yh = __float2bfloat16(y);
    float xr = x - __bfloat162float(xh);
    float yr = y - __bfloat162float(yh);
    __nv_bfloat162 h2, l2;
    h2.x = xh; h2.y = yh;
    l2.x = __float2bfloat16(xr); l2.y = __float2bfloat16(yr);
    hi = *reinterpret_cast<uint32_t*>(&h2);
    lo = *reinterpret_cast<uint32_t*>(&l2);
}

// Split two floats into packed fp16 hi/lo pairs
__device__ __forceinline__ void split2h(float x, float y, uint32_t& hi, uint32_t& lo) {
    __half xh = __float2half_rn(x);
    __half yh = __float2half_rn(y);
    float xr = x - __half2float(xh);
    float yr = y - __half2float(yh);
    __half2 h2, l2;
    h2.x = xh; h2.y = yh;
    l2.x = __float2half_rn(xr); l2.y = __float2half_rn(yr);
    hi = *reinterpret_cast<uint32_t*>(&h2);
    lo = *reinterpret_cast<uint32_t*>(&l2);
}

// ---------------------------------------------------------------------------
// 1) Elementwise split of x -> fp16 hi/lo
// ---------------------------------------------------------------------------
__global__ void split_x_kernel(const float4* __restrict__ X,
                               __half* __restrict__ Xh,
                               __half* __restrict__ Xl, int n4) {
    int i = blockIdx.x * blockDim.x + threadIdx.x;
    if (i >= n4) return;
    float4 v = X[i];
    uint32_t h0, l0, h1, l1;
    split2h(v.x, v.y, h0, l0);
    split2h(v.z, v.w, h1, l1);
    *(uint32_t*)(Xh + (size_t)i * 4)     = h0;
    *(uint32_t*)(Xh + (size_t)i * 4 + 2) = h1;
    *(uint32_t*)(Xl + (size_t)i * 4)     = l0;
    *(uint32_t*)(Xl + (size_t)i * 4 + 2) = l1;
}

// ---------------------------------------------------------------------------
// 2a) Transpose W[K,N] -> Wt fp16 single [N,K]
// ---------------------------------------------------------------------------
__global__ void transpose_f16_kernel(const float* __restrict__ W,
                                     __half* __restrict__ T, int K, int N) {
    __shared__ float t[32][33];
    int k0 = blockIdx.y * 32, n0 = blockIdx.x * 32;
    int tx = threadIdx.x & 31, ty = threadIdx.x >> 5;
#pragma unroll
    for (int i = 0; i < 4; i++)
        t[ty + 8 * i][tx] = W[(size_t)(k0 + ty + 8 * i) * N + n0 + tx];
    __syncthreads();
#pragma unroll
    for (int i = 0; i < 4; i++)
        T[(size_t)(n0 + ty + 8 * i) * K + k0 + tx] = __float2half_rn(t[tx][ty + 8 * i]);
}

// ---------------------------------------------------------------------------
// 2b) Transpose + split W[K,N] -> Wt bf16 hi/lo [N,K] (out-projection)
// ---------------------------------------------------------------------------
__global__ void transpose_split_kernel(const float* __restrict__ W,
                                       __nv_bfloat16* __restrict__ Th,
                                       __nv_bfloat16* __restrict__ Tl,
                                       int K, int N) {
    __shared__ float t[32][33];
    int k0 = blockIdx.y * 32, n0 = blockIdx.x * 32;
    int tx = threadIdx.x & 31, ty = threadIdx.x >> 5;
#pragma unroll
    for (int i = 0; i < 4; i++)
        t[ty + 8 * i][tx] = W[(size_t)(k0 + ty + 8 * i) * N + n0 + tx];
    __syncthreads();
#pragma unroll
    for (int i = 0; i < 4; i++) {
        float v = t[tx][ty + 8 * i];
        __nv_bfloat16 hi = __float2bfloat16(v);
        Th[(size_t)(n0 + ty + 8 * i) * K + k0 + tx] = hi;
        Tl[(size_t)(n0 + ty + 8 * i) * K + k0 + tx] =
            __float2bfloat16(v - __bfloat162float(hi));
    }
}

// ---------------------------------------------------------------------------
// 3a) QKV GEMM, 2-term fp16: C = (Ah+Al)[M,K] @ B[N,K]^T + bias
//     R2 pipeline skeleton: BK=16, 2-stage cp.async, 3 smem arrays.
// ---------------------------------------------------------------------------
__global__ __launch_bounds__(256)
void gemm_qkv_kernel(const __half* __restrict__ Ah, const __half* __restrict__ Al,
                     const __half* __restrict__ Bf,
                     const float* __restrict__ bias,
                     float* __restrict__ C, int M, int N, int K) {
    __shared__ __half sm[2][3][128][24];  // 36KB; arr: Ah, Al, B
    const int tid = threadIdx.x, lane = tid & 31, w = tid >> 5;
    const int wm = w >> 2, wn = w & 3;    // 2 x 4 warp grid
    const int brow = blockIdx.y * 128, bcol = blockIdx.x * 128;

    float c[4][4][4] = {};

    auto load_stage = [&](int s, int k0) {
#pragma unroll
        for (int i = 0; i < 3; i++) {
            int ch = tid + i * 256;   // 0..767
            int arr = ch >> 8;
            int r = (ch & 255) >> 1;
            int h8 = (ch & 1) * 8;
            const __half* g;
            if (arr == 0)      g = Ah + (size_t)(brow + r) * K + k0 + h8;
            else if (arr == 1) g = Al + (size_t)(brow + r) * K + k0 + h8;
            else               g = Bf + (size_t)(bcol + r) * K + k0 + h8;
            cpa16(smem_u32(&sm[s][arr][r][h8]), g);
        }
        asm volatile("cp.async.commit_group;");
    };

    const int NIT = K >> 4;
    load_stage(0, 0);
    for (int it = 0; it < NIT; ++it) {
        if (it + 1 < NIT) {
            load_stage((it + 1) & 1, (it + 1) * 16);
            asm volatile("cp.async.wait_group 1;");
        } else {
            asm volatile("cp.async.wait_group 0;");
        }
        __syncthreads();
        int s = it & 1;
        uint32_t ah[4][4], al[4][4];
#pragma unroll
        for (int mt = 0; mt < 4; mt++) {
            int row = wm * 64 + mt * 16 + (lane & 15);
            int col = (lane >> 4) * 8;
            ldsm4(ah[mt], &sm[s][0][row][col]);
            ldsm4(al[mt], &sm[s][1][row][col]);
        }
        uint32_t bf[4][2];
#pragma unroll
        for (int p = 0; p < 2; p++) {
            int row = wn * 32 + p * 16 + (lane & 15);
            int col = (lane >> 4) * 8;
            uint32_t t[4];
            ldsm4(t, &sm[s][2][row][col]);
            bf[2 * p][0] = t[0]; bf[2 * p][1] = t[2];
            bf[2 * p + 1][0] = t[1]; bf[2 * p + 1][1] = t[3];
        }
#pragma unroll
        for (int mt = 0; mt < 4; mt++)
#pragma unroll
            for (int nt = 0; nt < 4; nt++) {
                mma_f16(c[mt][nt], ah[mt], bf[nt]);
                mma_f16(c[mt][nt], al[mt], bf[nt]);
            }
        __syncthreads();
    }

    // Epilogue with bias
#pragma unroll
    for (int mt = 0; mt < 4; mt++) {
        int r0 = brow + wm * 64 + mt * 16 + (lane >> 2);
#pragma unroll
        for (int nt = 0; nt < 4; nt++) {
            int col = bcol + wn * 32 + nt * 8 + 2 * (lane & 3);
            float b0 = bias[col], b1 = bias[col + 1];
            float2 v0 = {c[mt][nt][0] + b0, c[mt][nt][1] + b1};
            float2 v1 = {c[mt][nt][2] + b0, c[mt][nt][3] + b1};
            *(float2*)(C + (size_t)r0 * N + col) = v0;
            *(float2*)(C + (size_t)(r0 + 8) * N + col) = v1;
        }
    }
}

// ---------------------------------------------------------------------------
// 3b) Out-projection GEMM, 3-term bf16 (EXACT R2 version)
// ---------------------------------------------------------------------------
__global__ __launch_bounds__(256)
void gemm_split_kernel(const __nv_bfloat16* __restrict__ Ah,
                       const __nv_bfloat16* __restrict__ Al,
                       const __nv_bfloat16* __restrict__ Bh,
                       const __nv_bfloat16* __restrict__ Bl,
                       const float* __restrict__ bias,
                       float* __restrict__ C, int M, int N, int K) {
    __shared__ __nv_bfloat16 sm[2][4][128][24];  // 48KB; arr: Ah,Al,Bh,Bl
    const int tid = threadIdx.x, lane = tid & 31, w = tid >> 5;
    const int wm = w >> 2, wn = w & 3;
    const int brow = blockIdx.y * 128, bcol = blockIdx.x * 128;

    float c[4][4][4] = {};

    auto load_stage = [&](int s, int k0) {
#pragma unroll
        for (int i = 0; i < 4; i++) {
            int ch = tid + i * 256;
            int arr = ch >> 8;
            int r = (ch & 255) >> 1;
            int h8 = (ch & 1) * 8;
            const __nv_bfloat16* g;
            if (arr == 0)      g = Ah + (size_t)(brow + r) * K + k0 + h8;
            else if (arr == 1) g = Al + (size_t)(brow + r) * K + k0 + h8;
            else if (arr == 2) g = Bh + (size_t)(bcol + r) * K + k0 + h8;
            else               g = Bl + (size_t)(bcol + r) * K + k0 + h8;
            cpa16(smem_u32(&sm[s][arr][r][h8]), g);
        }
        asm volatile("cp.async.commit_group;");
    };

    const int NIT = K >> 4;
    load_stage(0, 0);
    for (int it = 0; it < NIT; ++it) {
        if (it + 1 < NIT) {
            load_stage((it + 1) & 1, (it + 1) * 16);
            asm volatile("cp.async.wait_group 1;");
        } else {
            asm volatile("cp.async.wait_group 0;");
        }
        __syncthreads();
        int s = it & 1;
        uint32_t ah[4][4], al[4][4];
#pragma unroll
        for (int mt = 0; mt < 4; mt++) {
            int row = wm * 64 + mt * 16 + (lane & 15);
            int col = (lane >> 4) * 8;
            ldsm4(ah[mt], &sm[s][0][row][col]);
            ldsm4(al[mt], &sm[s][1][row][col]);
        }
        uint32_t bh[4][2], bl[4][2];
#pragma unroll
        for (int p = 0; p < 2; p++) {
            int row = wn * 32 + p * 16 + (lane & 15);
            int col = (lane >> 4) * 8;
            uint32_t t[4];
            ldsm4(t, &sm[s][2][row][col]);
            bh[2 * p][0] = t[0]; bh[2 * p][1] = t[2];
            bh[2 * p + 1][0] = t[1]; bh[2 * p + 1][1] = t[3];
            ldsm4(t, &sm[s][3][row][col]);
            bl[2 * p][0] = t[0]; bl[2 * p][1] = t[2];
            bl[2 * p + 1][0] = t[1]; bl[2 * p + 1][1] = t[3];
        }
#pragma unroll
        for (int mt = 0; mt < 4; mt++)
#pragma unroll
            for (int nt = 0; nt < 4; nt++) {
                mma_bf16(c[mt][nt], ah[mt], bh[nt]);
                mma_bf16(c[mt][nt], ah[mt], bl[nt]);
                mma_bf16(c[mt][nt], al[mt], bh[nt]);
            }
        __syncthreads();
    }

#pragma unroll
    for (int mt = 0; mt < 4; mt++) {
        int r0 = brow + wm * 64 + mt * 16 + (lane >> 2);
#pragma unroll
        for (int nt = 0; nt < 4; nt++) {
            int col = bcol + wn * 32 + nt * 8 + 2 * (lane & 3);
            float b0 = bias[col], b1 = bias[col + 1];
            float2 v0 = {c[mt][nt][0] + b0, c[mt][nt][1] + b1};
            float2 v1 = {c[mt][nt][2] + b0, c[mt][nt][3] + b1};
            *(float2*)(C + (size_t)r0 * N + col) = v0;
            *(float2*)(C + (size_t)(r0 + 8) * N + col) = v1;
        }
    }
}

// ---------------------------------------------------------------------------
// 4) Repack qkv fp32 -> per-head Q(scaled)/K fp16, V^T fp16 single
// ---------------------------------------------------------------------------
__global__ __launch_bounds__(256)
void repack_kernel(const float* __restrict__ qkv,
                   __half* __restrict__ Qf, __half* __restrict__ Kf,
                   __half* __restrict__ Vt) {
    __shared__ float vt[64][65];
    const int bh = blockIdx.y;
    const int b = bh >> 4, h = bh & 15;
    const int nb = blockIdx.x * 64;
    const float qscale = 0.125f * 1.4426950408889634f;  // scale * log2(e)

    for (int idx = threadIdx.x; idx < 64 * 192; idx += 256) {
        int r = idx / 192, cc = idx % 192;
        float v = qkv[(size_t)(b * N_ + nb + r) * QKV_N + h * 192 + cc];
        if (cc < 64) {
            Qf[((size_t)bh * N_ + nb + r) * 64 + cc] = __float2half_rn(v * qscale);
        } else if (cc < 128) {
            Kf[((size_t)bh * N_ + nb + r) * 64 + (cc - 64)] = __float2half_rn(v);
        } else {
            vt[cc - 128][r] = v;
        }
    }
    __syncthreads();
    for (int idx = threadIdx.x; idx < 64 * 64; idx += 256) {
        int d = idx >> 6, nl = idx & 63;
        Vt[((size_t)bh * 64 + d) * N_ + nb + nl] = __float2half_rn(vt[d][nl]);
    }
}

// ---------------------------------------------------------------------------
// 5) FA2 attention: single fp16 QK term, 2-term PV (P hi/lo x V single).
// ---------------------------------------------------------------------------
__global__ __launch_bounds__(256)
void attn_kernel(const __half* __restrict__ Qf, const __half* __restrict__ Kf,
                 const __half* __restrict__ Vt,
                 __nv_bfloat16* __restrict__ Oh, __nv_bfloat16* __restrict__ Ol) {
    __shared__ __half ks[64][72];       // K tile
    __shared__ __half vs[64][72];       // V tile, transposed [d][key]
    const int tid = threadIdx.x, lane = tid & 31, w = tid >> 5;
    const int bh = blockIdx.y, qb = blockIdx.x;
    const size_t qkbase = (size_t)bh * N_ * 64;
    const size_t vbase = (size_t)bh * 64 * N_;

    // Q fragments (fp16, pre-scaled) held in registers
    uint32_t qh[4][4];
    {
        int r0 = qb * 128 + w * 16 + (lane >> 2);
        int c0 = 2 * (lane & 3);
#pragma unroll
        for (int kd = 0; kd < 4; kd++) {
            const __half* ph = Qf + qkbase + (size_t)r0 * 64 + kd * 16 + c0;
            qh[kd][0] = *(const uint32_t*)(ph);
            qh[kd][1] = *(const uint32_t*)(ph + 8 * 64);
            qh[kd][2] = *(const uint32_t*)(ph + 8);
            qh[kd][3] = *(const uint32_t*)(ph + 8 * 64 + 8);
        }
    }

    float m0 = -1e30f, m1 = -1e30f, l0 = 0.f, l1 = 0.f;
    float o[8][4] = {};

    for (int kt0 = 0; kt0 < N_; kt0 += 64) {
        __syncthreads();
        // Load K (512 float4) + V (512) = 1024 chunks, 4/thread
#pragma unroll
        for (int i = 0; i < 4; i++) {
            int ch = tid + i * 256;         // 0..1023
            int arr = ch >> 9;
            int rem = ch & 511;
            int r = rem >> 3;
            int h8 = (rem & 7) * 8;
            if (arr == 0)
                *(float4*)&ks[r][h8] = *(const float4*)(Kf + qkbase + (size_t)(kt0 + r) * 64 + h8);
            else
                *(float4*)&vs[r][h8] = *(const float4*)(Vt + vbase + (size_t)r * N_ + kt0 + h8);
        }
        __syncthreads();

        // S = Q K^T (single fp16 term, pre-scaled log2 domain)
        float sc[8][4] = {};
#pragma unroll
        for (int kd = 0; kd < 4; kd++) {
            const int colb = kd * 16 + (lane >> 4) * 8;
            uint32_t kb[8][2];
#pragma unroll
            for (int p = 0; p < 4; p++) {
                int row = p * 16 + (lane & 15);
                uint32_t tt[4];
                ldsm4(tt, &ks[row][colb]);
                kb[2 * p][0] = tt[0]; kb[2 * p][1] = tt[2];
                kb[2 * p + 1][0] = tt[1]; kb[2 * p + 1][1] = tt[3];
            }
#pragma unroll
            for (int nt = 0; nt < 8; nt++)
                mma_f16(sc[nt], qh[kd], kb[nt]);
        }

        // Online softmax (base-2)
        float mx0 = -1e30f, mx1 = -1e30f;
#pragma unroll
        for (int nt = 0; nt < 8; nt++) {
            mx0 = fmaxf(mx0, fmaxf(sc[nt][0], sc[nt][1]));
            mx1 = fmaxf(mx1, fmaxf(sc[nt][2], sc[nt][3]));
        }
        mx0 = fmaxf(mx0, __shfl_xor_sync(0xffffffffu, mx0, 1));
        mx0 = fmaxf(mx0, __shfl_xor_sync(0xffffffffu, mx0, 2));
        mx1 = fmaxf(mx1, __shfl_xor_sync(0xffffffffu, mx1, 1));
        mx1 = fmaxf(mx1, __shfl_xor_sync(0xffffffffu, mx1, 2));
        float mn0 = fmaxf(m0, mx0), mn1 = fmaxf(m1, mx1);
        float a0 = ex2f(m0 - mn0), a1 = ex2f(m1 - mn1);
        m0 = mn0; m1 = mn1;

        float sum0 = 0.f, sum1 = 0.f;
#pragma unroll
        for (int nt = 0; nt < 8; nt++) {
            sc[nt][0] = ex2f(sc[nt][0] - mn0);
            sc[nt][1] = ex2f(sc[nt][1] - mn0);
            sc[nt][2] = ex2f(sc[nt][2] - mn1);
            sc[nt][3] = ex2f(sc[nt][3] - mn1);
            sum0 += sc[nt][0] + sc[nt][1];
            sum1 += sc[nt][2] + sc[nt][3];
        }
        sum0 += __shfl_xor_sync(0xffffffffu, sum0, 1);
        sum0 += __shfl_xor_sync(0xffffffffu, sum0, 2);
        sum1 += __shfl_xor_sync(0xffffffffu, sum1, 1);
        sum1 += __shfl_xor_sync(0xffffffffu, sum1, 2);
        l0 = l0 * a0 + sum0;
        l1 = l1 * a1 + sum1;
#pragma unroll
        for (int nd = 0; nd < 8; nd++) {
            o[nd][0] *= a0; o[nd][1] *= a0;
            o[nd][2] *= a1; o[nd][3] *= a1;
        }

        // P fragments, fp16 hi/lo (exact P up to fp16 pair)
        uint32_t pah[4][4], pal[4][4];
#pragma unroll
        for (int kt = 0; kt < 4; kt++) {
            split2h(sc[2 * kt][0], sc[2 * kt][1], pah[kt][0], pal[kt][0]);
            split2h(sc[2 * kt][2], sc[2 * kt][3], pah[kt][1], pal[kt][1]);
            split2h(sc[2 * kt + 1][0], sc[2 * kt + 1][1], pah[kt][2], pal[kt][2]);
            split2h(sc[2 * kt + 1][2], sc[2 * kt + 1][3], pah[kt][3], pal[kt][3]);
        }

        // O += P V (2-term: (Ph+Pl) x V)
#pragma unroll
        for (int kt = 0; kt < 4; kt++) {
            const int colb = kt * 16 + (lane >> 4) * 8;
            uint32_t vb[8][2];
#pragma unroll
            for (int p = 0; p < 4; p++) {
                int row = p * 16 + (lane & 15);
                uint32_t tt[4];
                ldsm4(tt, &vs[row][colb]);
                vb[2 * p][0] = tt[0]; vb[2 * p][1] = tt[2];
                vb[2 * p + 1][0] = tt[1]; vb[2 * p + 1][1] = tt[3];
            }
#pragma unroll
            for (int nd = 0; nd < 8; nd++) {
                mma_f16(o[nd], pah[kt], vb[nd]);
                mma_f16(o[nd], pal[kt], vb[nd]);
            }
        }
    }

    // Epilogue: normalize, split to bf16 hi/lo for out-projection
    float i0 = 1.f / l0, i1 = 1.f / l1;
    int b = bh >> 4, h = bh & 15;
    int r0 = b * N_ + qb * 128 + w * 16 + (lane >> 2);
#pragma unroll
    for (int nd = 0; nd < 8; nd++) {
        int col = h * 64 + nd * 8 + 2 * (lane & 3);
        uint32_t hi, lo;
        split2(o[nd][0] * i0, o[nd][1] * i0, hi, lo);
        *(uint32_t*)(Oh + (size_t)r0 * E_ + col) = hi;
        *(uint32_t*)(Ol + (size_t)r0 * E_ + col) = lo;
        split2(o[nd][2] * i1, o[nd][3] * i1, hi, lo);
        *(uint32_t*)(Oh + (size_t)(r0 + 8) * E_ + col) = hi;
        *(uint32_t*)(Ol + (size_t)(r0 + 8) * E_ + col) = lo;
    }
}

// ---------------------------------------------------------------------------
extern "C" void kernel_launch(void* const* d_in, const int* in_sizes, int n_in,
                              void* d_out, int out_size) {
    (void)in_sizes; (void)n_in; (void)out_size;
    const float* x     = (const float*)d_in[0];
    const float* W_qkv = (const float*)d_in[1];
    const float* b_qkv = (const float*)d_in[2];
    const float* W_out = (const float*)d_in[3];
    const float* b_out = (const float*)d_in[4];
    float* out = (float*)d_out;

    __nv_bfloat16 *woh, *wol, *o_h, *o_l;
    __half *wq, *xh, *xl, *q_f, *k_f, *v_t;
    float* qkv;
    cudaGetSymbolAddress((void**)&wq, g_wqkv);
    cudaGetSymbolAddress((void**)&woh, g_wout_h);
    cudaGetSymbolAddress((void**)&wol, g_wout_l);
    cudaGetSymbolAddress((void**)&xh, g_xh);
    cudaGetSymbolAddress((void**)&xl, g_xl);
    cudaGetSymbolAddress((void**)&qkv, g_qkv);
    cudaGetSymbolAddress((void**)&q_f, g_qf);
    cudaGetSymbolAddress((void**)&k_f, g_kf);
    cudaGetSymbolAddress((void**)&v_t, g_vt);
    cudaGetSymbolAddress((void**)&o_h, g_oh);
    cudaGetSymbolAddress((void**)&o_l, g_ol);

    // Prep: split x (fp16), transpose weights
    split_x_kernel<<<(M_TOT * E_ / 4 + 255) / 256, 256>>>((const float4*)x, xh, xl,
                                                          M_TOT * E_ / 4);
    transpose_f16_kernel<<<dim3(QKV_N / 32, E_ / 32), 256>>>(W_qkv, wq, E_, QKV_N);
    transpose_split_kernel<<<dim3(E_ / 32, E_ / 32), 256>>>(W_out, woh, wol, E_, E_);

    // QKV projection (2-term fp16)
    gemm_qkv_kernel<<<dim3(QKV_N / 128, M_TOT / 128), 256>>>(
        xh, xl, wq, b_qkv, qkv, M_TOT, QKV_N, E_);

    // Repack into per-head fp16 layouts
    repack_kernel<<<dim3(N_ / 64, BH_), 256>>>(qkv, q_f, k_f, v_t);

    // Attention
    attn_kernel<<<dim3(N_ / 128, BH_), 256>>>(q_f, k_f, v_t, o_h, o_l);

    // Output projection (3-term bf16)
    gemm_split_kernel<<<dim3(E_ / 128, M_TOT / 128), 256>>>(
        o_h, o_l, woh, wol, b_out, out, M_TOT, E_, E_);
}